// round 5
// baseline (speedup 1.0000x reference)
#include <cuda_runtime.h>
#include <math.h>

#define T_SEQ  2048
#define DIM_C  2048
#define NH     16
#define HD     128
#define QKV_N  6144      // 3 * 2048, row layout [t][e*2048 + h*128 + d]
#define ATTN_SCALE 0.12f

// Scratch
__device__ float g_qkv[(size_t)T_SEQ * QKV_N];        // 50 MB
__device__ float g_y[(size_t)T_SEQ * DIM_C];          // 16 MB
__device__ float g_wr[(size_t)4 * DIM_C * DIM_C];     // 64 MB (tf32-rounded w)
__device__ float g_xr[(size_t)T_SEQ * DIM_C];         // 16 MB (tf32-rounded x)

// ---------------------------------------------------------------------------
// helpers
// ---------------------------------------------------------------------------
__device__ __forceinline__ float tf32r(float x) {
    unsigned u;
    asm("cvt.rna.tf32.f32 %0, %1;" : "=r"(u) : "f"(x));
    return __uint_as_float(u);
}

__device__ __forceinline__ void mma_tf32(float* d, const float* a, const float* b) {
    asm volatile(
        "mma.sync.aligned.m16n8k8.row.col.f32.tf32.tf32.f32 "
        "{%0,%1,%2,%3}, {%4,%5,%6,%7}, {%8,%9}, {%0,%1,%2,%3};\n"
        : "+f"(d[0]), "+f"(d[1]), "+f"(d[2]), "+f"(d[3])
        : "r"(__float_as_uint(a[0])), "r"(__float_as_uint(a[1])),
          "r"(__float_as_uint(a[2])), "r"(__float_as_uint(a[3])),
          "r"(__float_as_uint(b[0])), "r"(__float_as_uint(b[1])));
}

__device__ __forceinline__ unsigned smem_u32(const void* p) {
    return (unsigned)__cvta_generic_to_shared(p);
}

// ldmatrix: a-frag (m16k8 tf32) = 4 8x8-b16 tiles; b-frag = 2 tiles.
__device__ __forceinline__ void ldsm4(float* r, unsigned addr) {
    unsigned* u = (unsigned*)r;
    asm volatile("ldmatrix.sync.aligned.m8n8.x4.shared.b16 {%0,%1,%2,%3}, [%4];"
                 : "=r"(u[0]), "=r"(u[1]), "=r"(u[2]), "=r"(u[3]) : "r"(addr));
}
__device__ __forceinline__ void ldsm2(float* r, unsigned addr) {
    unsigned* u = (unsigned*)r;
    asm volatile("ldmatrix.sync.aligned.m8n8.x2.shared.b16 {%0,%1}, [%2];"
                 : "=r"(u[0]), "=r"(u[1]) : "r"(addr));
}

#define CP16(dst, src) \
    asm volatile("cp.async.cg.shared.global [%0], [%1], 16;" :: "r"(dst), "l"(src))
#define CPCOMMIT() asm volatile("cp.async.commit_group;")
#define CPWAIT1()  asm volatile("cp.async.wait_group 1;" ::: "memory")

// ---------------------------------------------------------------------------
// tf32 rounding pass (x, w -> scratch, once)
// ---------------------------------------------------------------------------
__global__ void round_tf32_kernel(const float4* __restrict__ src,
                                  float4* __restrict__ dst, int n4)
{
    for (int i = blockIdx.x * blockDim.x + threadIdx.x; i < n4;
         i += gridDim.x * blockDim.x) {
        float4 v = src[i];
        dst[i] = make_float4(tf32r(v.x), tf32r(v.y), tf32r(v.z), tf32r(v.w));
    }
}

// ---------------------------------------------------------------------------
// GEMM (TN): C[m][n] = sum_k A[m*K+k] * B[n*K+k].  Inputs pre-rounded tf32.
// 128x128 tile, BK=32, 8 warps (2x4), warp tile 64x32.
// cp.async 2-stage + ldmatrix fragment loads.
// smem rows pitch 36 floats (144B): LDSM row addrs at 4-bank offsets: clean.
// ---------------------------------------------------------------------------
#define GSPAD 36
#define GBUF  (128 * GSPAD)

__global__ __launch_bounds__(256, 2)
void gemm_tf32_kernel(const float* __restrict__ A,
                      const float* __restrict__ B,
                      float* __restrict__ C,
                      int M, int N, int K)
{
    extern __shared__ float smg[];
    float* As = smg;                 // [2][128][36]
    float* Bs = smg + 2 * GBUF;

    const int tid  = threadIdx.x;
    const int lane = tid & 31;
    const int wid  = tid >> 5;
    const int g    = lane >> 2;
    const int tig  = lane & 3;
    const int wm   = (wid & 1) * 64;
    const int wn   = (wid >> 1) * 32;

    const int rowBase = blockIdx.y * 128;
    const int colBase = blockIdx.x * 128;
    const float* Ag = A + (size_t)rowBase * K;
    const float* Bg = B + (size_t)colBase * K;

    const int r0 = tid >> 3;
    const int c4 = (tid & 7) << 2;

    // ldmatrix per-lane source addresses (buffer 0, ks 0)
    const int arow = (lane & 7) + ((lane >> 3) & 1) * 8;
    const int acol = (lane >> 4) * 4;
    const int bl   = lane & 15;
    const int brow = bl & 7;
    const int bcol = ((bl >> 3) & 1) * 4;

    unsigned aAddr[4], bAddr[4];
#pragma unroll
    for (int mi = 0; mi < 4; mi++)
        aAddr[mi] = smem_u32(&As[(wm + mi * 16 + arow) * GSPAD + acol]);
#pragma unroll
    for (int ni = 0; ni < 4; ni++)
        bAddr[ni] = smem_u32(&Bs[(wn + ni * 8 + brow) * GSPAD + bcol]);

    const unsigned asA = smem_u32(As);
    const unsigned asB = smem_u32(Bs);
    const unsigned BUFB = GBUF * 4;   // bytes per stage

    float acc[4][4][4];
#pragma unroll
    for (int mi = 0; mi < 4; mi++)
#pragma unroll
        for (int ni = 0; ni < 4; ni++)
#pragma unroll
            for (int c = 0; c < 4; c++) acc[mi][ni][c] = 0.0f;

    // prologue: stage 0
#pragma unroll
    for (int i = 0; i < 4; i++) {
        int r = r0 + 32 * i;
        CP16(asA + (unsigned)((r * GSPAD + c4) * 4), Ag + (size_t)r * K + c4);
        CP16(asB + (unsigned)((r * GSPAD + c4) * 4), Bg + (size_t)r * K + c4);
    }
    CPCOMMIT();

    const int nk = K >> 5;
    for (int kt = 0; kt < nk; kt++) {
        const int buf = kt & 1;
        if (kt + 1 < nk) {
            const int k0 = (kt + 1) << 5;
            const unsigned boff = (buf ^ 1) * BUFB;
#pragma unroll
            for (int i = 0; i < 4; i++) {
                int r = r0 + 32 * i;
                CP16(asA + boff + (unsigned)((r * GSPAD + c4) * 4),
                     Ag + (size_t)r * K + k0 + c4);
                CP16(asB + boff + (unsigned)((r * GSPAD + c4) * 4),
                     Bg + (size_t)r * K + k0 + c4);
            }
        }
        CPCOMMIT();
        CPWAIT1();
        __syncthreads();

        const unsigned cOff = buf * BUFB;
#pragma unroll
        for (int ks = 0; ks < 4; ks++) {
            const unsigned kOff = cOff + ks * 32;
            float a[4][4], b[4][2];
#pragma unroll
            for (int mi = 0; mi < 4; mi++) ldsm4(a[mi], aAddr[mi] + kOff);
#pragma unroll
            for (int ni = 0; ni < 4; ni++) ldsm2(b[ni], bAddr[ni] + kOff);
#pragma unroll
            for (int mi = 0; mi < 4; mi++)
#pragma unroll
                for (int ni = 0; ni < 4; ni++)
                    mma_tf32(acc[mi][ni], a[mi], b[ni]);
        }
        __syncthreads();
    }

    float* Cp = C + (size_t)rowBase * N + colBase;
#pragma unroll
    for (int mi = 0; mi < 4; mi++) {
        int m = wm + mi * 16 + g;
#pragma unroll
        for (int ni = 0; ni < 4; ni++) {
            int n = wn + ni * 8 + tig * 2;
            *(float2*)&Cp[(size_t)m * N + n] =
                make_float2(acc[mi][ni][0], acc[mi][ni][1]);
            *(float2*)&Cp[(size_t)(m + 8) * N + n] =
                make_float2(acc[mi][ni][2], acc[mi][ni][3]);
        }
    }
}

// ---------------------------------------------------------------------------
// Per (t, h): RMSNorm q/k/v, RoPE q/k, v blend. Writes tf32-rounded values.
// ---------------------------------------------------------------------------
__global__ void postproc_kernel(const float* __restrict__ ve,
                                const float* __restrict__ lam)
{
    const int t = blockIdx.x;
    const int h = blockIdx.y;
    const int d = threadIdx.x;

    __shared__ float red[4];
    __shared__ float buf[128];

    float* base = g_qkv + (size_t)t * QKV_N + h * HD;
    const float lam0 = lam[0];
    const float lam1 = lam[1];

#pragma unroll
    for (int e = 0; e < 3; e++) {
        float val = base[e * 2048 + d];
        float sq = val * val;
#pragma unroll
        for (int o = 16; o > 0; o >>= 1)
            sq += __shfl_xor_sync(0xffffffffu, sq, o);
        if ((d & 31) == 0) red[d >> 5] = sq;
        __syncthreads();
        float mean = (red[0] + red[1] + red[2] + red[3]) * (1.0f / 128.0f);
        float nv = val * rsqrtf(mean + 1e-6f);

        if (e < 2) {
            buf[d] = nv;
            __syncthreads();
            int j = d & 63;
            float c, sn;
            if (j < 32) {
                float fr = exp2f((-10.0f / 31.0f) * (float)j);
                float th = (float)t * fr;
                c = cosf(th); sn = sinf(th);
            } else {
                c = 1.0f; sn = 0.0f;
            }
            float x1 = buf[j];
            float x2 = buf[j + 64];
            float outv = (d < 64) ? (x1 * c + x2 * sn) : (x2 * c - x1 * sn);
            __syncthreads();
            base[e * 2048 + d] = tf32r(outv);
        } else {
            base[e * 2048 + d] =
                tf32r(lam0 * nv + lam1 * ve[(size_t)t * DIM_C + h * HD + d]);
        }
    }
}

// ---------------------------------------------------------------------------
// Causal flash attention (tf32 mma + ldmatrix). Q-tile 64, KV-tile 64.
// 8 warps: wid&3 -> q-row block, wid>>2 -> col half. Ps aliases Ks.
// ---------------------------------------------------------------------------
#define AQ_OFF   0
#define AKU_OFF  (64 * 132)
#define AV_OFF   (AKU_OFF + 64 * 132)
#define ARM_OFF  (AV_OFF + 128 * 68)
#define ARS_OFF  (ARM_OFF + 128)
#define ATTN_SMEM ((ARS_OFF + 128) * 4)     // 103,424 B

__global__ __launch_bounds__(256, 2)
void attn_kernel()
{
    extern __shared__ float sm[];
    float* Qs    = sm + AQ_OFF;
    float* Ks    = sm + AKU_OFF;
    float* Ps    = sm + AKU_OFF;   // alias
    float* Vst   = sm + AV_OFF;
    float* rpmax = sm + ARM_OFF;
    float* rpsum = sm + ARS_OFF;

    const int h     = blockIdx.y;
    const int qt    = 31 - (int)blockIdx.x;
    const int qbase = qt * 64;
    const int tid   = threadIdx.x;
    const int lane  = tid & 31;
    const int wid   = tid >> 5;
    const int g     = lane >> 2;
    const int tig   = lane & 3;
    const int rw    = (wid & 3) * 16;
    const int ch    = wid >> 2;

    // ldmatrix lane-address components
    const int arow = (lane & 7) + ((lane >> 3) & 1) * 8;
    const int acol = (lane >> 4) * 4;
    const int bl   = lane & 15;
    const int brow = bl & 7;
    const int bcol = ((bl >> 3) & 1) * 4;

    const unsigned qAddr = smem_u32(&Qs[(rw + arow) * 132 + acol]);
    const unsigned pAddr = smem_u32(&Ps[(rw + arow) * 68 + acol]);
    const unsigned kBase = smem_u32(&Ks[(ch * 32 + brow) * 132 + bcol]);
    const unsigned vBase = smem_u32(&Vst[(ch * 64 + brow) * 68 + bcol]);

    // Q tile (already tf32)
    const float* qg = g_qkv + (size_t)qbase * QKV_N + h * HD;
#pragma unroll
    for (int f = tid; f < 64 * 32; f += 256) {
        int r = f >> 5, d4 = (f & 31) << 2;
        *(float4*)&Qs[r * 132 + d4] = *(const float4*)(qg + (size_t)r * QKV_N + d4);
    }

    float oacc[8][4];
#pragma unroll
    for (int nd = 0; nd < 8; nd++)
#pragma unroll
        for (int c = 0; c < 4; c++) oacc[nd][c] = 0.0f;

    float m0 = -INFINITY, m1 = -INFINITY, l0 = 0.0f, l1 = 0.0f;

    const int row0 = qbase + rw + g;
    const int row1 = row0 + 8;

    __syncthreads();

    for (int kb = 0; kb <= qt; kb++) {
        // ---- phase A: load K and V tiles ----
        const float* kg = g_qkv + (size_t)(kb * 64) * QKV_N + 2048 + h * HD;
#pragma unroll
        for (int f = tid; f < 64 * 32; f += 256) {
            int c = f >> 5, d4 = (f & 31) << 2;
            *(float4*)&Ks[c * 132 + d4] = *(const float4*)(kg + (size_t)c * QKV_N + d4);
        }
        const float* vg = g_qkv + (size_t)(kb * 64) * QKV_N + 4096 + h * HD;
#pragma unroll
        for (int f = tid; f < 64 * 32; f += 256) {
            int d4 = (f >> 6) << 2, c = f & 63;
            float4 v = *(const float4*)(vg + (size_t)c * QKV_N + d4);
            Vst[(d4 + 0) * 68 + c] = v.x;
            Vst[(d4 + 1) * 68 + c] = v.y;
            Vst[(d4 + 2) * 68 + c] = v.z;
            Vst[(d4 + 3) * 68 + c] = v.w;
        }
        __syncthreads();   // B1

        // ---- phase B: S = Q K^T ----
        float sacc[4][4];
#pragma unroll
        for (int ni = 0; ni < 4; ni++)
#pragma unroll
            for (int c = 0; c < 4; c++) sacc[ni][c] = 0.0f;

#pragma unroll
        for (int kk = 0; kk < 16; kk++) {
            float a[4];
            ldsm4(a, qAddr + kk * 32);
#pragma unroll
            for (int ni = 0; ni < 4; ni++) {
                float b[2];
                ldsm2(b, kBase + ni * (8 * 132 * 4) + kk * 32);
                mma_tf32(sacc[ni], a, b);
            }
        }

        // scale + mask + partial row max
        const int cbase = kb * 64 + ch * 32;
        const bool needmask = (kb == qt);
        float rmax0 = -INFINITY, rmax1 = -INFINITY;
#pragma unroll
        for (int ni = 0; ni < 4; ni++) {
            int c0 = cbase + ni * 8 + 2 * tig;
            float v0 = sacc[ni][0] * ATTN_SCALE;
            float v1 = sacc[ni][1] * ATTN_SCALE;
            float v2 = sacc[ni][2] * ATTN_SCALE;
            float v3 = sacc[ni][3] * ATTN_SCALE;
            if (needmask) {
                if (c0     > row0) v0 = -INFINITY;
                if (c0 + 1 > row0) v1 = -INFINITY;
                if (c0     > row1) v2 = -INFINITY;
                if (c0 + 1 > row1) v3 = -INFINITY;
            }
            sacc[ni][0] = v0; sacc[ni][1] = v1;
            sacc[ni][2] = v2; sacc[ni][3] = v3;
            rmax0 = fmaxf(rmax0, fmaxf(v0, v1));
            rmax1 = fmaxf(rmax1, fmaxf(v2, v3));
        }
        rmax0 = fmaxf(rmax0, __shfl_xor_sync(0xffffffffu, rmax0, 1));
        rmax0 = fmaxf(rmax0, __shfl_xor_sync(0xffffffffu, rmax0, 2));
        rmax1 = fmaxf(rmax1, __shfl_xor_sync(0xffffffffu, rmax1, 1));
        rmax1 = fmaxf(rmax1, __shfl_xor_sync(0xffffffffu, rmax1, 2));
        if (tig == 0) {
            rpmax[(rw + g) * 2 + ch]     = rmax0;
            rpmax[(rw + g + 8) * 2 + ch] = rmax1;
        }
        __syncthreads();   // B2

        // ---- phase C: softmax, write P (aliases Ks) ----
        float mt0 = fmaxf(rpmax[(rw + g) * 2],     rpmax[(rw + g) * 2 + 1]);
        float mt1 = fmaxf(rpmax[(rw + g + 8) * 2], rpmax[(rw + g + 8) * 2 + 1]);
        float mn0 = fmaxf(m0, mt0);
        float mn1 = fmaxf(m1, mt1);
        float fr0 = __expf(m0 - mn0);
        float fr1 = __expf(m1 - mn1);
        m0 = mn0; m1 = mn1;

        float sum0 = 0.0f, sum1 = 0.0f;
#pragma unroll
        for (int ni = 0; ni < 4; ni++) {
            float p0 = __expf(sacc[ni][0] - mn0);
            float p1 = __expf(sacc[ni][1] - mn0);
            float p2 = __expf(sacc[ni][2] - mn1);
            float p3 = __expf(sacc[ni][3] - mn1);
            sum0 += p0 + p1;
            sum1 += p2 + p3;
            int cc = ch * 32 + ni * 8 + 2 * tig;
            *(float2*)&Ps[(rw + g) * 68 + cc]     = make_float2(tf32r(p0), tf32r(p1));
            *(float2*)&Ps[(rw + g + 8) * 68 + cc] = make_float2(tf32r(p2), tf32r(p3));
        }
        sum0 += __shfl_xor_sync(0xffffffffu, sum0, 1);
        sum0 += __shfl_xor_sync(0xffffffffu, sum0, 2);
        sum1 += __shfl_xor_sync(0xffffffffu, sum1, 1);
        sum1 += __shfl_xor_sync(0xffffffffu, sum1, 2);
        if (tig == 0) {
            rpsum[(rw + g) * 2 + ch]     = sum0;
            rpsum[(rw + g + 8) * 2 + ch] = sum1;
        }
        __syncthreads();   // B3

        // ---- phase D: l update, rescale, O += P V ----
        float st0 = rpsum[(rw + g) * 2]     + rpsum[(rw + g) * 2 + 1];
        float st1 = rpsum[(rw + g + 8) * 2] + rpsum[(rw + g + 8) * 2 + 1];
        l0 = l0 * fr0 + st0;
        l1 = l1 * fr1 + st1;
#pragma unroll
        for (int nd = 0; nd < 8; nd++) {
            oacc[nd][0] *= fr0; oacc[nd][1] *= fr0;
            oacc[nd][2] *= fr1; oacc[nd][3] *= fr1;
        }

#pragma unroll
        for (int ss = 0; ss < 8; ss++) {
            float a[4];
            ldsm4(a, pAddr + ss * 32);
#pragma unroll
            for (int nd = 0; nd < 8; nd++) {
                float b[2];
                ldsm2(b, vBase + nd * (8 * 68 * 4) + ss * 32);
                mma_tf32(oacc[nd], a, b);
            }
        }
        __syncthreads();   // B4
    }

    // epilogue: normalize, tf32-round (output GEMM consumes directly)
    const float inv0 = 1.0f / l0;
    const float inv1 = 1.0f / l1;
    float* dst0 = g_y + (size_t)row0 * DIM_C + h * HD + ch * 64;
    float* dst1 = g_y + (size_t)row1 * DIM_C + h * HD + ch * 64;
#pragma unroll
    for (int nd = 0; nd < 8; nd++) {
        int col = nd * 8 + 2 * tig;
        *(float2*)&dst0[col] =
            make_float2(tf32r(oacc[nd][0] * inv0), tf32r(oacc[nd][1] * inv0));
        *(float2*)&dst1[col] =
            make_float2(tf32r(oacc[nd][2] * inv1), tf32r(oacc[nd][3] * inv1));
    }
}

// ---------------------------------------------------------------------------
extern "C" void kernel_launch(void* const* d_in, const int* in_sizes, int n_in,
                              void* d_out, int out_size)
{
    const float* x   = (const float*)d_in[0];   // [1,2048,2048]
    const float* w   = (const float*)d_in[1];   // [4,2048,2048]
    const float* ve  = (const float*)d_in[2];   // [1,2048,2048]
    const float* lam = (const float*)d_in[3];   // [2]
    float* out = (float*)d_out;                 // [1,2048,2048] f32

    float *qkv_ptr = nullptr, *y_ptr = nullptr, *wr_ptr = nullptr, *xr_ptr = nullptr;
    cudaGetSymbolAddress((void**)&qkv_ptr, g_qkv);
    cudaGetSymbolAddress((void**)&y_ptr,   g_y);
    cudaGetSymbolAddress((void**)&wr_ptr,  g_wr);
    cudaGetSymbolAddress((void**)&xr_ptr,  g_xr);

    // 0) pre-round x, w to tf32
    round_tf32_kernel<<<2048, 256>>>((const float4*)x, (float4*)xr_ptr,
                                     T_SEQ * DIM_C / 4);
    round_tf32_kernel<<<4096, 256>>>((const float4*)w, (float4*)wr_ptr,
                                     4 * DIM_C * DIM_C / 4);

    const int gemm_smem = 4 * GBUF * (int)sizeof(float);   // 73728 B
    cudaFuncSetAttribute(gemm_tf32_kernel,
                         cudaFuncAttributeMaxDynamicSharedMemorySize, gemm_smem);

    // 1) QKV projection
    gemm_tf32_kernel<<<dim3(48, 16), 256, gemm_smem>>>(xr_ptr, wr_ptr, qkv_ptr,
                                                       2048, 6144, 2048);

    // 2) RMSNorm + RoPE + v blend (writes tf32-rounded q/k/v)
    postproc_kernel<<<dim3(2048, 16), 128>>>(ve, lam);

    // 3) causal attention (writes tf32-rounded y)
    cudaFuncSetAttribute(attn_kernel,
                         cudaFuncAttributeMaxDynamicSharedMemorySize, ATTN_SMEM);
    attn_kernel<<<dim3(32, 16), 256, ATTN_SMEM>>>();

    // 4) output projection
    gemm_tf32_kernel<<<dim3(16, 16), 256, gemm_smem>>>(
        y_ptr, wr_ptr + (size_t)3 * DIM_C * DIM_C, out, 2048, 2048, 2048);
}

// round 6
// speedup vs baseline: 1.4937x; 1.4937x over previous
#include <cuda_runtime.h>
#include <math.h>

#define T_SEQ  2048
#define DIM_C  2048
#define NH     16
#define HD     128
#define QKV_N  6144      // 3 * 2048, row layout [t][e*2048 + h*128 + d]
#define ATTN_SCALE 0.12f

// Scratch
__device__ float g_qkv[(size_t)T_SEQ * QKV_N];        // 50 MB
__device__ float g_y[(size_t)T_SEQ * DIM_C];          // 16 MB
__device__ float g_wr[(size_t)4 * DIM_C * DIM_C];     // 64 MB (tf32-rounded w)
__device__ float g_xr[(size_t)T_SEQ * DIM_C];         // 16 MB (tf32-rounded x)

// ---------------------------------------------------------------------------
// helpers
// ---------------------------------------------------------------------------
__device__ __forceinline__ float tf32r(float x) {
    unsigned u;
    asm("cvt.rna.tf32.f32 %0, %1;" : "=r"(u) : "f"(x));
    return __uint_as_float(u);
}

__device__ __forceinline__ void mma_tf32(float* d, const float* a, const float* b) {
    asm volatile(
        "mma.sync.aligned.m16n8k8.row.col.f32.tf32.tf32.f32 "
        "{%0,%1,%2,%3}, {%4,%5,%6,%7}, {%8,%9}, {%0,%1,%2,%3};\n"
        : "+f"(d[0]), "+f"(d[1]), "+f"(d[2]), "+f"(d[3])
        : "r"(__float_as_uint(a[0])), "r"(__float_as_uint(a[1])),
          "r"(__float_as_uint(a[2])), "r"(__float_as_uint(a[3])),
          "r"(__float_as_uint(b[0])), "r"(__float_as_uint(b[1])));
}

__device__ __forceinline__ unsigned smem_u32(const void* p) {
    return (unsigned)__cvta_generic_to_shared(p);
}

__device__ __forceinline__ void ldsm4(float* r, unsigned addr) {
    unsigned* u = (unsigned*)r;
    asm volatile("ldmatrix.sync.aligned.m8n8.x4.shared.b16 {%0,%1,%2,%3}, [%4];"
                 : "=r"(u[0]), "=r"(u[1]), "=r"(u[2]), "=r"(u[3]) : "r"(addr));
}
__device__ __forceinline__ void ldsm2(float* r, unsigned addr) {
    unsigned* u = (unsigned*)r;
    asm volatile("ldmatrix.sync.aligned.m8n8.x2.shared.b16 {%0,%1}, [%2];"
                 : "=r"(u[0]), "=r"(u[1]) : "r"(addr));
}

#define CP16(dst, src) \
    asm volatile("cp.async.cg.shared.global [%0], [%1], 16;" :: "r"(dst), "l"(src))
#define CPCOMMIT() asm volatile("cp.async.commit_group;")
#define CPWAIT1()  asm volatile("cp.async.wait_group 1;" ::: "memory")

// ---------------------------------------------------------------------------
// tf32 rounding pass (x, w -> scratch, once)
// ---------------------------------------------------------------------------
__global__ void round_tf32_kernel(const float4* __restrict__ src,
                                  float4* __restrict__ dst, int n4)
{
    for (int i = blockIdx.x * blockDim.x + threadIdx.x; i < n4;
         i += gridDim.x * blockDim.x) {
        float4 v = src[i];
        dst[i] = make_float4(tf32r(v.x), tf32r(v.y), tf32r(v.z), tf32r(v.w));
    }
}

// ---------------------------------------------------------------------------
// GEMM (TN): C[m][n] = sum_k A[m*K+k] * B[n*K+k].  Inputs pre-rounded tf32.
// 128x128 tile, BK=32, 8 warps (2x4), warp tile 64x32.
// 3-stage cp.async ring, ONE __syncthreads per k-iter, ldmatrix frag loads.
// Pitch 36 floats (144B = 16B-aligned, ldmatrix rows at 4-bank offsets).
// ---------------------------------------------------------------------------
#define GSPAD   36
#define GBUF    (128 * GSPAD)
#define GSTAGES 3

__global__ __launch_bounds__(256, 2)
void gemm_tf32_kernel(const float* __restrict__ A,
                      const float* __restrict__ B,
                      float* __restrict__ C,
                      int M, int N, int K)
{
    extern __shared__ float smg[];
    float* As = smg;                         // [3][128][36]
    float* Bs = smg + GSTAGES * GBUF;        // [3][128][36]

    const int tid  = threadIdx.x;
    const int lane = tid & 31;
    const int wid  = tid >> 5;
    const int g    = lane >> 2;
    const int tig  = lane & 3;
    const int wm   = (wid & 1) * 64;
    const int wn   = (wid >> 1) * 32;

    const int rowBase = blockIdx.y * 128;
    const int colBase = blockIdx.x * 128;
    const float* Ag = A + (size_t)rowBase * K;
    const float* Bg = B + (size_t)colBase * K;

    const int r0 = tid >> 3;          // 0..31, +32*i
    const int c4 = (tid & 7) << 2;    // 0..28

    // ldmatrix lane addressing (validated in R5: rel_err identical to scalar)
    const int arow = (lane & 7) + ((lane >> 3) & 1) * 8;
    const int acol = (lane >> 4) * 4;
    const int bl   = lane & 15;
    const int brow = bl & 7;
    const int bcol = ((bl >> 3) & 1) * 4;

    unsigned aAddr[4], bAddr[4];
#pragma unroll
    for (int mi = 0; mi < 4; mi++)
        aAddr[mi] = smem_u32(&As[(wm + mi * 16 + arow) * GSPAD + acol]);
#pragma unroll
    for (int ni = 0; ni < 4; ni++)
        bAddr[ni] = smem_u32(&Bs[(wn + ni * 8 + brow) * GSPAD + bcol]);

    const unsigned asA = smem_u32(As);
    const unsigned asB = smem_u32(Bs);
    const unsigned STGB = GBUF * 4;   // bytes per stage
    const unsigned dstOff = (unsigned)((r0 * GSPAD + c4) * 4);

    float acc[4][4][4];
#pragma unroll
    for (int mi = 0; mi < 4; mi++)
#pragma unroll
        for (int ni = 0; ni < 4; ni++)
#pragma unroll
            for (int c = 0; c < 4; c++) acc[mi][ni][c] = 0.0f;

    const int nk = K >> 5;   // 64

    // prologue: stages 0 and 1, one commit group each
#pragma unroll
    for (int s = 0; s < GSTAGES - 1; s++) {
        const unsigned so = s * STGB;
        const int k0 = s << 5;
#pragma unroll
        for (int i = 0; i < 4; i++) {
            int r = r0 + 32 * i;
            CP16(asA + so + dstOff + (unsigned)(i * 32 * GSPAD * 4),
                 Ag + (size_t)r * K + k0 + c4);
            CP16(asB + so + dstOff + (unsigned)(i * 32 * GSPAD * 4),
                 Bg + (size_t)r * K + k0 + c4);
        }
        CPCOMMIT();
    }

    int slot = 0;
    for (int kt = 0; kt < nk; kt++) {
        CPWAIT1();            // stage kt resident (≤1 younger group pending)
        __syncthreads();      // all warps done reading slot (kt-1)%3

        // prefetch stage kt+2 into slot (kt+2)%3 == (kt-1)%3  (safe post-barrier)
        if (kt + GSTAGES - 1 < nk) {
            const int ks = kt + GSTAGES - 1;
            const unsigned so = (unsigned)(ks % GSTAGES) * STGB;
            const int k0 = ks << 5;
#pragma unroll
            for (int i = 0; i < 4; i++) {
                int r = r0 + 32 * i;
                CP16(asA + so + dstOff + (unsigned)(i * 32 * GSPAD * 4),
                     Ag + (size_t)r * K + k0 + c4);
                CP16(asB + so + dstOff + (unsigned)(i * 32 * GSPAD * 4),
                     Bg + (size_t)r * K + k0 + c4);
            }
        }
        CPCOMMIT();           // commit every iter (may be empty): keeps count exact

        const unsigned cOff = (unsigned)slot * STGB;
#pragma unroll
        for (int ks = 0; ks < 4; ks++) {
            const unsigned kOff = cOff + ks * 32;
            float a[4][4], b[4][2];
#pragma unroll
            for (int mi = 0; mi < 4; mi++) ldsm4(a[mi], aAddr[mi] + kOff);
#pragma unroll
            for (int ni = 0; ni < 4; ni++) ldsm2(b[ni], bAddr[ni] + kOff);
#pragma unroll
            for (int mi = 0; mi < 4; mi++)
#pragma unroll
                for (int ni = 0; ni < 4; ni++)
                    mma_tf32(acc[mi][ni], a[mi], b[ni]);
        }
        slot = (slot + 1 == GSTAGES) ? 0 : slot + 1;
    }

    float* Cp = C + (size_t)rowBase * N + colBase;
#pragma unroll
    for (int mi = 0; mi < 4; mi++) {
        int m = wm + mi * 16 + g;
#pragma unroll
        for (int ni = 0; ni < 4; ni++) {
            int n = wn + ni * 8 + tig * 2;
            *(float2*)&Cp[(size_t)m * N + n] =
                make_float2(acc[mi][ni][0], acc[mi][ni][1]);
            *(float2*)&Cp[(size_t)(m + 8) * N + n] =
                make_float2(acc[mi][ni][2], acc[mi][ni][3]);
        }
    }
}

// ---------------------------------------------------------------------------
// Per (t, h): RMSNorm q/k/v, RoPE q/k, v blend. Writes tf32-rounded values.
// ---------------------------------------------------------------------------
__global__ void postproc_kernel(const float* __restrict__ ve,
                                const float* __restrict__ lam)
{
    const int t = blockIdx.x;
    const int h = blockIdx.y;
    const int d = threadIdx.x;

    __shared__ float red[4];
    __shared__ float buf[128];

    float* base = g_qkv + (size_t)t * QKV_N + h * HD;
    const float lam0 = lam[0];
    const float lam1 = lam[1];

#pragma unroll
    for (int e = 0; e < 3; e++) {
        float val = base[e * 2048 + d];
        float sq = val * val;
#pragma unroll
        for (int o = 16; o > 0; o >>= 1)
            sq += __shfl_xor_sync(0xffffffffu, sq, o);
        if ((d & 31) == 0) red[d >> 5] = sq;
        __syncthreads();
        float mean = (red[0] + red[1] + red[2] + red[3]) * (1.0f / 128.0f);
        float nv = val * rsqrtf(mean + 1e-6f);

        if (e < 2) {
            buf[d] = nv;
            __syncthreads();
            int j = d & 63;
            float c, sn;
            if (j < 32) {
                float fr = exp2f((-10.0f / 31.0f) * (float)j);
                float th = (float)t * fr;
                c = cosf(th); sn = sinf(th);
            } else {
                c = 1.0f; sn = 0.0f;
            }
            float x1 = buf[j];
            float x2 = buf[j + 64];
            float outv = (d < 64) ? (x1 * c + x2 * sn) : (x2 * c - x1 * sn);
            __syncthreads();
            base[e * 2048 + d] = tf32r(outv);
        } else {
            base[e * 2048 + d] =
                tf32r(lam0 * nv + lam1 * ve[(size_t)t * DIM_C + h * HD + d]);
        }
    }
}

// ---------------------------------------------------------------------------
// Causal flash attention (tf32 mma + ldmatrix). Q-tile 64, KV-tile 64.
// 8 warps: wid&3 -> q-row block, wid>>2 -> col half. Ps aliases Ks.
// ---------------------------------------------------------------------------
#define AQ_OFF   0
#define AKU_OFF  (64 * 132)
#define AV_OFF   (AKU_OFF + 64 * 132)
#define ARM_OFF  (AV_OFF + 128 * 68)
#define ARS_OFF  (ARM_OFF + 128)
#define ATTN_SMEM ((ARS_OFF + 128) * 4)     // 103,424 B

__global__ __launch_bounds__(256, 2)
void attn_kernel()
{
    extern __shared__ float sm[];
    float* Qs    = sm + AQ_OFF;
    float* Ks    = sm + AKU_OFF;
    float* Ps    = sm + AKU_OFF;   // alias
    float* Vst   = sm + AV_OFF;
    float* rpmax = sm + ARM_OFF;
    float* rpsum = sm + ARS_OFF;

    const int h     = blockIdx.y;
    const int qt    = 31 - (int)blockIdx.x;
    const int qbase = qt * 64;
    const int tid   = threadIdx.x;
    const int lane  = tid & 31;
    const int wid   = tid >> 5;
    const int g     = lane >> 2;
    const int tig   = lane & 3;
    const int rw    = (wid & 3) * 16;
    const int ch    = wid >> 2;

    const int arow = (lane & 7) + ((lane >> 3) & 1) * 8;
    const int acol = (lane >> 4) * 4;
    const int bl   = lane & 15;
    const int brow = bl & 7;
    const int bcol = ((bl >> 3) & 1) * 4;

    const unsigned qAddr = smem_u32(&Qs[(rw + arow) * 132 + acol]);
    const unsigned pAddr = smem_u32(&Ps[(rw + arow) * 68 + acol]);
    const unsigned kBase = smem_u32(&Ks[(ch * 32 + brow) * 132 + bcol]);
    const unsigned vBase = smem_u32(&Vst[(ch * 64 + brow) * 68 + bcol]);

    const float* qg = g_qkv + (size_t)qbase * QKV_N + h * HD;
#pragma unroll
    for (int f = tid; f < 64 * 32; f += 256) {
        int r = f >> 5, d4 = (f & 31) << 2;
        *(float4*)&Qs[r * 132 + d4] = *(const float4*)(qg + (size_t)r * QKV_N + d4);
    }

    float oacc[8][4];
#pragma unroll
    for (int nd = 0; nd < 8; nd++)
#pragma unroll
        for (int c = 0; c < 4; c++) oacc[nd][c] = 0.0f;

    float m0 = -INFINITY, m1 = -INFINITY, l0 = 0.0f, l1 = 0.0f;

    const int row0 = qbase + rw + g;
    const int row1 = row0 + 8;

    __syncthreads();

    for (int kb = 0; kb <= qt; kb++) {
        // ---- phase A: load K and V tiles ----
        const float* kg = g_qkv + (size_t)(kb * 64) * QKV_N + 2048 + h * HD;
#pragma unroll
        for (int f = tid; f < 64 * 32; f += 256) {
            int c = f >> 5, d4 = (f & 31) << 2;
            *(float4*)&Ks[c * 132 + d4] = *(const float4*)(kg + (size_t)c * QKV_N + d4);
        }
        const float* vg = g_qkv + (size_t)(kb * 64) * QKV_N + 4096 + h * HD;
#pragma unroll
        for (int f = tid; f < 64 * 32; f += 256) {
            int d4 = (f >> 6) << 2, c = f & 63;
            float4 v = *(const float4*)(vg + (size_t)c * QKV_N + d4);
            Vst[(d4 + 0) * 68 + c] = v.x;
            Vst[(d4 + 1) * 68 + c] = v.y;
            Vst[(d4 + 2) * 68 + c] = v.z;
            Vst[(d4 + 3) * 68 + c] = v.w;
        }
        __syncthreads();   // B1

        // ---- phase B: S = Q K^T ----
        float sacc[4][4];
#pragma unroll
        for (int ni = 0; ni < 4; ni++)
#pragma unroll
            for (int c = 0; c < 4; c++) sacc[ni][c] = 0.0f;

#pragma unroll
        for (int kk = 0; kk < 16; kk++) {
            float a[4];
            ldsm4(a, qAddr + kk * 32);
#pragma unroll
            for (int ni = 0; ni < 4; ni++) {
                float b[2];
                ldsm2(b, kBase + ni * (8 * 132 * 4) + kk * 32);
                mma_tf32(sacc[ni], a, b);
            }
        }

        const int cbase = kb * 64 + ch * 32;
        const bool needmask = (kb == qt);
        float rmax0 = -INFINITY, rmax1 = -INFINITY;
#pragma unroll
        for (int ni = 0; ni < 4; ni++) {
            int c0 = cbase + ni * 8 + 2 * tig;
            float v0 = sacc[ni][0] * ATTN_SCALE;
            float v1 = sacc[ni][1] * ATTN_SCALE;
            float v2 = sacc[ni][2] * ATTN_SCALE;
            float v3 = sacc[ni][3] * ATTN_SCALE;
            if (needmask) {
                if (c0     > row0) v0 = -INFINITY;
                if (c0 + 1 > row0) v1 = -INFINITY;
                if (c0     > row1) v2 = -INFINITY;
                if (c0 + 1 > row1) v3 = -INFINITY;
            }
            sacc[ni][0] = v0; sacc[ni][1] = v1;
            sacc[ni][2] = v2; sacc[ni][3] = v3;
            rmax0 = fmaxf(rmax0, fmaxf(v0, v1));
            rmax1 = fmaxf(rmax1, fmaxf(v2, v3));
        }
        rmax0 = fmaxf(rmax0, __shfl_xor_sync(0xffffffffu, rmax0, 1));
        rmax0 = fmaxf(rmax0, __shfl_xor_sync(0xffffffffu, rmax0, 2));
        rmax1 = fmaxf(rmax1, __shfl_xor_sync(0xffffffffu, rmax1, 1));
        rmax1 = fmaxf(rmax1, __shfl_xor_sync(0xffffffffu, rmax1, 2));
        if (tig == 0) {
            rpmax[(rw + g) * 2 + ch]     = rmax0;
            rpmax[(rw + g + 8) * 2 + ch] = rmax1;
        }
        __syncthreads();   // B2

        // ---- phase C: softmax, write P (aliases Ks) ----
        float mt0 = fmaxf(rpmax[(rw + g) * 2],     rpmax[(rw + g) * 2 + 1]);
        float mt1 = fmaxf(rpmax[(rw + g + 8) * 2], rpmax[(rw + g + 8) * 2 + 1]);
        float mn0 = fmaxf(m0, mt0);
        float mn1 = fmaxf(m1, mt1);
        float fr0 = __expf(m0 - mn0);
        float fr1 = __expf(m1 - mn1);
        m0 = mn0; m1 = mn1;

        float sum0 = 0.0f, sum1 = 0.0f;
#pragma unroll
        for (int ni = 0; ni < 4; ni++) {
            float p0 = __expf(sacc[ni][0] - mn0);
            float p1 = __expf(sacc[ni][1] - mn0);
            float p2 = __expf(sacc[ni][2] - mn1);
            float p3 = __expf(sacc[ni][3] - mn1);
            sum0 += p0 + p1;
            sum1 += p2 + p3;
            int cc = ch * 32 + ni * 8 + 2 * tig;
            *(float2*)&Ps[(rw + g) * 68 + cc]     = make_float2(tf32r(p0), tf32r(p1));
            *(float2*)&Ps[(rw + g + 8) * 68 + cc] = make_float2(tf32r(p2), tf32r(p3));
        }
        sum0 += __shfl_xor_sync(0xffffffffu, sum0, 1);
        sum0 += __shfl_xor_sync(0xffffffffu, sum0, 2);
        sum1 += __shfl_xor_sync(0xffffffffu, sum1, 1);
        sum1 += __shfl_xor_sync(0xffffffffu, sum1, 2);
        if (tig == 0) {
            rpsum[(rw + g) * 2 + ch]     = sum0;
            rpsum[(rw + g + 8) * 2 + ch] = sum1;
        }
        __syncthreads();   // B3

        // ---- phase D: l update, rescale, O += P V ----
        float st0 = rpsum[(rw + g) * 2]     + rpsum[(rw + g) * 2 + 1];
        float st1 = rpsum[(rw + g + 8) * 2] + rpsum[(rw + g + 8) * 2 + 1];
        l0 = l0 * fr0 + st0;
        l1 = l1 * fr1 + st1;
#pragma unroll
        for (int nd = 0; nd < 8; nd++) {
            oacc[nd][0] *= fr0; oacc[nd][1] *= fr0;
            oacc[nd][2] *= fr1; oacc[nd][3] *= fr1;
        }

#pragma unroll
        for (int ss = 0; ss < 8; ss++) {
            float a[4];
            ldsm4(a, pAddr + ss * 32);
#pragma unroll
            for (int nd = 0; nd < 8; nd++) {
                float b[2];
                ldsm2(b, vBase + nd * (8 * 68 * 4) + ss * 32);
                mma_tf32(oacc[nd], a, b);
            }
        }
        __syncthreads();   // B4
    }

    const float inv0 = 1.0f / l0;
    const float inv1 = 1.0f / l1;
    float* dst0 = g_y + (size_t)row0 * DIM_C + h * HD + ch * 64;
    float* dst1 = g_y + (size_t)row1 * DIM_C + h * HD + ch * 64;
#pragma unroll
    for (int nd = 0; nd < 8; nd++) {
        int col = nd * 8 + 2 * tig;
        *(float2*)&dst0[col] =
            make_float2(tf32r(oacc[nd][0] * inv0), tf32r(oacc[nd][1] * inv0));
        *(float2*)&dst1[col] =
            make_float2(tf32r(oacc[nd][2] * inv1), tf32r(oacc[nd][3] * inv1));
    }
}

// ---------------------------------------------------------------------------
extern "C" void kernel_launch(void* const* d_in, const int* in_sizes, int n_in,
                              void* d_out, int out_size)
{
    const float* x   = (const float*)d_in[0];   // [1,2048,2048]
    const float* w   = (const float*)d_in[1];   // [4,2048,2048]
    const float* ve  = (const float*)d_in[2];   // [1,2048,2048]
    const float* lam = (const float*)d_in[3];   // [2]
    float* out = (float*)d_out;                 // [1,2048,2048] f32

    float *qkv_ptr = nullptr, *y_ptr = nullptr, *wr_ptr = nullptr, *xr_ptr = nullptr;
    cudaGetSymbolAddress((void**)&qkv_ptr, g_qkv);
    cudaGetSymbolAddress((void**)&y_ptr,   g_y);
    cudaGetSymbolAddress((void**)&wr_ptr,  g_wr);
    cudaGetSymbolAddress((void**)&xr_ptr,  g_xr);

    // 0) pre-round x, w to tf32
    round_tf32_kernel<<<2048, 256>>>((const float4*)x, (float4*)xr_ptr,
                                     T_SEQ * DIM_C / 4);
    round_tf32_kernel<<<4096, 256>>>((const float4*)w, (float4*)wr_ptr,
                                     4 * DIM_C * DIM_C / 4);

    const int gemm_smem = GSTAGES * 2 * GBUF * (int)sizeof(float);   // 110,592 B
    cudaFuncSetAttribute(gemm_tf32_kernel,
                         cudaFuncAttributeMaxDynamicSharedMemorySize, gemm_smem);

    // 1) QKV projection
    gemm_tf32_kernel<<<dim3(48, 16), 256, gemm_smem>>>(xr_ptr, wr_ptr, qkv_ptr,
                                                       2048, 6144, 2048);

    // 2) RMSNorm + RoPE + v blend (writes tf32-rounded q/k/v)
    postproc_kernel<<<dim3(2048, 16), 128>>>(ve, lam);

    // 3) causal attention (writes tf32-rounded y)
    cudaFuncSetAttribute(attn_kernel,
                         cudaFuncAttributeMaxDynamicSharedMemorySize, ATTN_SMEM);
    attn_kernel<<<dim3(32, 16), 256, ATTN_SMEM>>>();

    // 4) output projection
    gemm_tf32_kernel<<<dim3(16, 16), 256, gemm_smem>>>(
        y_ptr, wr_ptr + (size_t)3 * DIM_C * DIM_C, out, 2048, 2048, 2048);
}

// round 8
// speedup vs baseline: 1.5576x; 1.0428x over previous
#include <cuda_runtime.h>
#include <math.h>

#define T_SEQ  2048
#define DIM_C  2048
#define NH     16
#define HD     128
#define QKV_N  6144      // 3 * 2048, row layout [t][e*2048 + h*128 + d]
#define ATTN_SCALE 0.12f

// Scratch
__device__ float g_qkv[(size_t)T_SEQ * QKV_N];        // 50 MB
__device__ float g_y[(size_t)T_SEQ * DIM_C];          // 16 MB
__device__ float g_wr[(size_t)4 * DIM_C * DIM_C];     // 64 MB (tf32-rounded w)
__device__ float g_xr[(size_t)T_SEQ * DIM_C];         // 16 MB (tf32-rounded x)

// ---------------------------------------------------------------------------
// helpers
// ---------------------------------------------------------------------------
__device__ __forceinline__ float tf32r(float x) {
    unsigned u;
    asm("cvt.rna.tf32.f32 %0, %1;" : "=r"(u) : "f"(x));
    return __uint_as_float(u);
}

__device__ __forceinline__ void mma_tf32(float* d, const float* a, const float* b) {
    asm volatile(
        "mma.sync.aligned.m16n8k8.row.col.f32.tf32.tf32.f32 "
        "{%0,%1,%2,%3}, {%4,%5,%6,%7}, {%8,%9}, {%0,%1,%2,%3};\n"
        : "+f"(d[0]), "+f"(d[1]), "+f"(d[2]), "+f"(d[3])
        : "r"(__float_as_uint(a[0])), "r"(__float_as_uint(a[1])),
          "r"(__float_as_uint(a[2])), "r"(__float_as_uint(a[3])),
          "r"(__float_as_uint(b[0])), "r"(__float_as_uint(b[1])));
}

__device__ __forceinline__ unsigned smem_u32(const void* p) {
    return (unsigned)__cvta_generic_to_shared(p);
}

__device__ __forceinline__ void ldsm4(float* r, unsigned addr) {
    unsigned* u = (unsigned*)r;
    asm volatile("ldmatrix.sync.aligned.m8n8.x4.shared.b16 {%0,%1,%2,%3}, [%4];"
                 : "=r"(u[0]), "=r"(u[1]), "=r"(u[2]), "=r"(u[3]) : "r"(addr));
}

#define CP16(dst, src) \
    asm volatile("cp.async.cg.shared.global [%0], [%1], 16;" :: "r"(dst), "l"(src))
#define CPCOMMIT() asm volatile("cp.async.commit_group;")
#define CPWAIT1()  asm volatile("cp.async.wait_group 1;" ::: "memory")
#define CPWAIT0()  asm volatile("cp.async.wait_group 0;" ::: "memory")

// ---------------------------------------------------------------------------
// tf32 rounding pass (x, w -> scratch, once)
// ---------------------------------------------------------------------------
__global__ void round_tf32_kernel(const float4* __restrict__ src,
                                  float4* __restrict__ dst, int n4)
{
    for (int i = blockIdx.x * blockDim.x + threadIdx.x; i < n4;
         i += gridDim.x * blockDim.x) {
        float4 v = src[i];
        dst[i] = make_float4(tf32r(v.x), tf32r(v.y), tf32r(v.z), tf32r(v.w));
    }
}

// ---------------------------------------------------------------------------
// GEMM (TN): C[m][n] = sum_k A[m*K+k] * B[n*K+k].  Inputs pre-rounded tf32.
// 128x128 tile, BK=32, 8 warps (2x4), warp tile 64x32.
// 3-stage cp.async ring, one __syncthreads per k-iter, paired-B ldmatrix.x4.
// ---------------------------------------------------------------------------
#define GSPAD   36
#define GBUF    (128 * GSPAD)
#define GSTAGES 3

__global__ __launch_bounds__(256, 2)
void gemm_tf32_kernel(const float* __restrict__ A,
                      const float* __restrict__ B,
                      float* __restrict__ C,
                      int M, int N, int K)
{
    extern __shared__ float smg[];
    float* As = smg;                         // [3][128][36]
    float* Bs = smg + GSTAGES * GBUF;        // [3][128][36]

    const int tid  = threadIdx.x;
    const int lane = tid & 31;
    const int wid  = tid >> 5;
    const int g    = lane >> 2;
    const int tig  = lane & 3;
    const int wm   = (wid & 1) * 64;
    const int wn   = (wid >> 1) * 32;

    const int rowBase = blockIdx.y * 128;
    const int colBase = blockIdx.x * 128;
    const float* Ag = A + (size_t)rowBase * K;
    const float* Bg = B + (size_t)colBase * K;

    const int r0 = tid >> 3;
    const int c4 = (tid & 7) << 2;

    // ldmatrix lane addressing
    const int arow = (lane & 7) + ((lane >> 3) & 1) * 8;
    const int acol = (lane >> 4) * 4;
    const int tl   = lane >> 3;                    // tile index 0..3
    const int brow = (lane & 7) + (tl >> 1) * 8;   // tiles 2,3 -> +8 rows
    const int bcol = (tl & 1) * 4;                 // tiles 1,3 -> k+4

    unsigned aAddr[4], bAddr[2];
#pragma unroll
    for (int mi = 0; mi < 4; mi++)
        aAddr[mi] = smem_u32(&As[(wm + mi * 16 + arow) * GSPAD + acol]);
#pragma unroll
    for (int p = 0; p < 2; p++)
        bAddr[p] = smem_u32(&Bs[(wn + p * 16 + brow) * GSPAD + bcol]);

    const unsigned asA = smem_u32(As);
    const unsigned asB = smem_u32(Bs);
    const unsigned STGB = GBUF * 4;
    const unsigned dstOff = (unsigned)((r0 * GSPAD + c4) * 4);

    float acc[4][4][4];
#pragma unroll
    for (int mi = 0; mi < 4; mi++)
#pragma unroll
        for (int ni = 0; ni < 4; ni++)
#pragma unroll
            for (int c = 0; c < 4; c++) acc[mi][ni][c] = 0.0f;

    const int nk = K >> 5;

    // prologue: stages 0,1
#pragma unroll
    for (int s = 0; s < GSTAGES - 1; s++) {
        const unsigned so = s * STGB;
        const int k0 = s << 5;
#pragma unroll
        for (int i = 0; i < 4; i++) {
            int r = r0 + 32 * i;
            CP16(asA + so + dstOff + (unsigned)(i * 32 * GSPAD * 4),
                 Ag + (size_t)r * K + k0 + c4);
            CP16(asB + so + dstOff + (unsigned)(i * 32 * GSPAD * 4),
                 Bg + (size_t)r * K + k0 + c4);
        }
        CPCOMMIT();
    }

    int slot = 0;
    for (int kt = 0; kt < nk; kt++) {
        CPWAIT1();
        __syncthreads();

        if (kt + GSTAGES - 1 < nk) {
            const int ks = kt + GSTAGES - 1;
            const unsigned so = (unsigned)(ks % GSTAGES) * STGB;
            const int k0 = ks << 5;
#pragma unroll
            for (int i = 0; i < 4; i++) {
                int r = r0 + 32 * i;
                CP16(asA + so + dstOff + (unsigned)(i * 32 * GSPAD * 4),
                     Ag + (size_t)r * K + k0 + c4);
                CP16(asB + so + dstOff + (unsigned)(i * 32 * GSPAD * 4),
                     Bg + (size_t)r * K + k0 + c4);
            }
        }
        CPCOMMIT();

        const unsigned cOff = (unsigned)slot * STGB;
#pragma unroll
        for (int ks = 0; ks < 4; ks++) {
            const unsigned kOff = cOff + ks * 32;
            float a[4][4], bq[2][4];
#pragma unroll
            for (int mi = 0; mi < 4; mi++) ldsm4(a[mi], aAddr[mi] + kOff);
#pragma unroll
            for (int p = 0; p < 2; p++) ldsm4(bq[p], bAddr[p] + kOff);
#pragma unroll
            for (int mi = 0; mi < 4; mi++)
#pragma unroll
                for (int p = 0; p < 2; p++) {
                    mma_tf32(acc[mi][2 * p],     a[mi], &bq[p][0]);
                    mma_tf32(acc[mi][2 * p + 1], a[mi], &bq[p][2]);
                }
        }
        slot = (slot + 1 == GSTAGES) ? 0 : slot + 1;
    }

    float* Cp = C + (size_t)rowBase * N + colBase;
#pragma unroll
    for (int mi = 0; mi < 4; mi++) {
        int m = wm + mi * 16 + g;
#pragma unroll
        for (int ni = 0; ni < 4; ni++) {
            int n = wn + ni * 8 + tig * 2;
            *(float2*)&Cp[(size_t)m * N + n] =
                make_float2(acc[mi][ni][0], acc[mi][ni][1]);
            *(float2*)&Cp[(size_t)(m + 8) * N + n] =
                make_float2(acc[mi][ni][2], acc[mi][ni][3]);
        }
    }
}

// ---------------------------------------------------------------------------
// Per (t, h): RMSNorm q/k/v, RoPE q/k, v blend. Writes tf32-rounded values.
// ---------------------------------------------------------------------------
__global__ void postproc_kernel(const float* __restrict__ ve,
                                const float* __restrict__ lam)
{
    const int t = blockIdx.x;
    const int h = blockIdx.y;
    const int d = threadIdx.x;

    __shared__ float red[4];
    __shared__ float buf[128];

    float* base = g_qkv + (size_t)t * QKV_N + h * HD;
    const float lam0 = lam[0];
    const float lam1 = lam[1];

#pragma unroll
    for (int e = 0; e < 3; e++) {
        float val = base[e * 2048 + d];
        float sq = val * val;
#pragma unroll
        for (int o = 16; o > 0; o >>= 1)
            sq += __shfl_xor_sync(0xffffffffu, sq, o);
        if ((d & 31) == 0) red[d >> 5] = sq;
        __syncthreads();
        float mean = (red[0] + red[1] + red[2] + red[3]) * (1.0f / 128.0f);
        float nv = val * rsqrtf(mean + 1e-6f);

        if (e < 2) {
            buf[d] = nv;
            __syncthreads();
            int j = d & 63;
            float c, sn;
            if (j < 32) {
                float fr = exp2f((-10.0f / 31.0f) * (float)j);
                float th = (float)t * fr;
                c = cosf(th); sn = sinf(th);
            } else {
                c = 1.0f; sn = 0.0f;
            }
            float x1 = buf[j];
            float x2 = buf[j + 64];
            float outv = (d < 64) ? (x1 * c + x2 * sn) : (x2 * c - x1 * sn);
            __syncthreads();
            base[e * 2048 + d] = tf32r(outv);
        } else {
            base[e * 2048 + d] =
                tf32r(lam0 * nv + lam1 * ve[(size_t)t * DIM_C + h * HD + d]);
        }
    }
}

// ---------------------------------------------------------------------------
// Causal flash attention (tf32 mma + paired ldmatrix.x4). Q-tile 64, KV 64.
// 8 warps: wid&3 -> q-row block, wid>>2 -> col half. Ps aliases Ks.
// 4 barriers/tile (P-write -> P-read barrier is cross-warp and required).
// ---------------------------------------------------------------------------
#define AQ_OFF   0
#define AKU_OFF  (64 * 132)
#define AV_OFF   (AKU_OFF + 64 * 132)
#define ARM_OFF  (AV_OFF + 128 * 68)
#define ARS_OFF  (ARM_OFF + 128)
#define ATTN_SMEM ((ARS_OFF + 128) * 4)     // 103,424 B

__global__ __launch_bounds__(256, 2)
void attn_kernel()
{
    extern __shared__ float sm[];
    float* Qs    = sm + AQ_OFF;
    float* Ks    = sm + AKU_OFF;
    float* Ps    = sm + AKU_OFF;   // alias
    float* Vst   = sm + AV_OFF;
    float* rpmax = sm + ARM_OFF;
    float* rpsum = sm + ARS_OFF;

    const int h     = blockIdx.y;
    const int qt    = 31 - (int)blockIdx.x;
    const int qbase = qt * 64;
    const int tid   = threadIdx.x;
    const int lane  = tid & 31;
    const int wid   = tid >> 5;
    const int g     = lane >> 2;
    const int tig   = lane & 3;
    const int rw    = (wid & 3) * 16;
    const int ch    = wid >> 2;

    const int arow = (lane & 7) + ((lane >> 3) & 1) * 8;
    const int acol = (lane >> 4) * 4;
    const int tl   = lane >> 3;
    const int brow = (lane & 7) + (tl >> 1) * 8;
    const int bcol = (tl & 1) * 4;

    const unsigned qAddr = smem_u32(&Qs[(rw + arow) * 132 + acol]);
    const unsigned pAddr = smem_u32(&Ps[(rw + arow) * 68 + acol]);
    unsigned kAddr[2], vAddr[4];
#pragma unroll
    for (int p = 0; p < 2; p++)
        kAddr[p] = smem_u32(&Ks[(ch * 32 + p * 16 + brow) * 132 + bcol]);
#pragma unroll
    for (int p = 0; p < 4; p++)
        vAddr[p] = smem_u32(&Vst[(ch * 64 + p * 16 + brow) * 68 + bcol]);

    const unsigned ksBase = smem_u32(Ks);

    const float* qg = g_qkv + (size_t)qbase * QKV_N + h * HD;
#pragma unroll
    for (int f = tid; f < 64 * 32; f += 256) {
        int r = f >> 5, d4 = (f & 31) << 2;
        *(float4*)&Qs[r * 132 + d4] = *(const float4*)(qg + (size_t)r * QKV_N + d4);
    }

    float oacc[8][4];
#pragma unroll
    for (int nd = 0; nd < 8; nd++)
#pragma unroll
        for (int c = 0; c < 4; c++) oacc[nd][c] = 0.0f;

    float m0 = -INFINITY, m1 = -INFINITY, l0 = 0.0f, l1 = 0.0f;

    const int row0 = qbase + rw + g;
    const int row1 = row0 + 8;

    __syncthreads();

    for (int kb = 0; kb <= qt; kb++) {
        // ---- phase A: K via cp.async (FULL tile: 8 CP16/thread), V manual ----
        const float* kg = g_qkv + (size_t)(kb * 64) * QKV_N + 2048 + h * HD;
#pragma unroll
        for (int f = tid; f < 64 * 32; f += 256) {
            int c = f >> 5, d4 = (f & 31) << 2;
            CP16(ksBase + (unsigned)((c * 132 + d4) * 4),
                 kg + (size_t)c * QKV_N + d4);
        }
        CPCOMMIT();
        const float* vg = g_qkv + (size_t)(kb * 64) * QKV_N + 4096 + h * HD;
#pragma unroll
        for (int f = tid; f < 64 * 32; f += 256) {
            int d4 = (f >> 6) << 2, c = f & 63;
            float4 v = *(const float4*)(vg + (size_t)c * QKV_N + d4);
            Vst[(d4 + 0) * 68 + c] = v.x;
            Vst[(d4 + 1) * 68 + c] = v.y;
            Vst[(d4 + 2) * 68 + c] = v.z;
            Vst[(d4 + 3) * 68 + c] = v.w;
        }
        CPWAIT0();
        __syncthreads();   // B1

        // ---- phase B: S = Q K^T (paired x4 B-frags) ----
        float sacc[4][4];
#pragma unroll
        for (int ni = 0; ni < 4; ni++)
#pragma unroll
            for (int c = 0; c < 4; c++) sacc[ni][c] = 0.0f;

#pragma unroll
        for (int kk = 0; kk < 16; kk++) {
            float a[4], bq[2][4];
            ldsm4(a, qAddr + kk * 32);
#pragma unroll
            for (int p = 0; p < 2; p++) {
                ldsm4(bq[p], kAddr[p] + kk * 32);
                mma_tf32(sacc[2 * p],     a, &bq[p][0]);
                mma_tf32(sacc[2 * p + 1], a, &bq[p][2]);
            }
        }

        const int cbase = kb * 64 + ch * 32;
        const bool needmask = (kb == qt);
        float rmax0 = -INFINITY, rmax1 = -INFINITY;
#pragma unroll
        for (int ni = 0; ni < 4; ni++) {
            int c0 = cbase + ni * 8 + 2 * tig;
            float v0 = sacc[ni][0] * ATTN_SCALE;
            float v1 = sacc[ni][1] * ATTN_SCALE;
            float v2 = sacc[ni][2] * ATTN_SCALE;
            float v3 = sacc[ni][3] * ATTN_SCALE;
            if (needmask) {
                if (c0     > row0) v0 = -INFINITY;
                if (c0 + 1 > row0) v1 = -INFINITY;
                if (c0     > row1) v2 = -INFINITY;
                if (c0 + 1 > row1) v3 = -INFINITY;
            }
            sacc[ni][0] = v0; sacc[ni][1] = v1;
            sacc[ni][2] = v2; sacc[ni][3] = v3;
            rmax0 = fmaxf(rmax0, fmaxf(v0, v1));
            rmax1 = fmaxf(rmax1, fmaxf(v2, v3));
        }
        rmax0 = fmaxf(rmax0, __shfl_xor_sync(0xffffffffu, rmax0, 1));
        rmax0 = fmaxf(rmax0, __shfl_xor_sync(0xffffffffu, rmax0, 2));
        rmax1 = fmaxf(rmax1, __shfl_xor_sync(0xffffffffu, rmax1, 1));
        rmax1 = fmaxf(rmax1, __shfl_xor_sync(0xffffffffu, rmax1, 2));
        if (tig == 0) {
            rpmax[(rw + g) * 2 + ch]     = rmax0;
            rpmax[(rw + g + 8) * 2 + ch] = rmax1;
        }
        __syncthreads();   // B2 (Ks consumed; rpmax visible)

        // ---- phase C: softmax, write P half ----
        float mt0 = fmaxf(rpmax[(rw + g) * 2],     rpmax[(rw + g) * 2 + 1]);
        float mt1 = fmaxf(rpmax[(rw + g + 8) * 2], rpmax[(rw + g + 8) * 2 + 1]);
        float mn0 = fmaxf(m0, mt0);
        float mn1 = fmaxf(m1, mt1);
        float fr0 = __expf(m0 - mn0);
        float fr1 = __expf(m1 - mn1);
        m0 = mn0; m1 = mn1;

        float sum0 = 0.0f, sum1 = 0.0f;
#pragma unroll
        for (int ni = 0; ni < 4; ni++) {
            float p0 = __expf(sacc[ni][0] - mn0);
            float p1 = __expf(sacc[ni][1] - mn0);
            float p2 = __expf(sacc[ni][2] - mn1);
            float p3 = __expf(sacc[ni][3] - mn1);
            sum0 += p0 + p1;
            sum1 += p2 + p3;
            int cc = ch * 32 + ni * 8 + 2 * tig;
            *(float2*)&Ps[(rw + g) * 68 + cc]     = make_float2(tf32r(p0), tf32r(p1));
            *(float2*)&Ps[(rw + g + 8) * 68 + cc] = make_float2(tf32r(p2), tf32r(p3));
        }
        sum0 += __shfl_xor_sync(0xffffffffu, sum0, 1);
        sum0 += __shfl_xor_sync(0xffffffffu, sum0, 2);
        sum1 += __shfl_xor_sync(0xffffffffu, sum1, 1);
        sum1 += __shfl_xor_sync(0xffffffffu, sum1, 2);
        // per-col-half partial l (same m/fr sequence both halves; combine at end)
        l0 = l0 * fr0 + sum0;
        l1 = l1 * fr1 + sum1;
        __syncthreads();   // B3 (P read below spans BOTH col halves: cross-warp)

        // ---- phase D: rescale, O += P V (paired x4) ----
#pragma unroll
        for (int nd = 0; nd < 8; nd++) {
            oacc[nd][0] *= fr0; oacc[nd][1] *= fr0;
            oacc[nd][2] *= fr1; oacc[nd][3] *= fr1;
        }

#pragma unroll
        for (int ss = 0; ss < 8; ss++) {
            float a[4], bq[4];
            ldsm4(a, pAddr + ss * 32);
#pragma unroll
            for (int p = 0; p < 4; p++) {
                ldsm4(bq, vAddr[p] + ss * 32);
                mma_tf32(oacc[2 * p],     a, &bq[0]);
                mma_tf32(oacc[2 * p + 1], a, &bq[2]);
            }
        }
        __syncthreads();   // B4 (Ps/Vst consumed before next tile load)
    }

    // epilogue: combine per-half l, normalize, tf32-round
    if (tig == 0) {
        rpsum[(rw + g) * 2 + ch]     = l0;
        rpsum[(rw + g + 8) * 2 + ch] = l1;
    }
    __syncthreads();
    const float lt0 = rpsum[(rw + g) * 2]     + rpsum[(rw + g) * 2 + 1];
    const float lt1 = rpsum[(rw + g + 8) * 2] + rpsum[(rw + g + 8) * 2 + 1];
    const float inv0 = 1.0f / lt0;
    const float inv1 = 1.0f / lt1;
    float* dst0 = g_y + (size_t)row0 * DIM_C + h * HD + ch * 64;
    float* dst1 = g_y + (size_t)row1 * DIM_C + h * HD + ch * 64;
#pragma unroll
    for (int nd = 0; nd < 8; nd++) {
        int col = nd * 8 + 2 * tig;
        *(float2*)&dst0[col] =
            make_float2(tf32r(oacc[nd][0] * inv0), tf32r(oacc[nd][1] * inv0));
        *(float2*)&dst1[col] =
            make_float2(tf32r(oacc[nd][2] * inv1), tf32r(oacc[nd][3] * inv1));
    }
}

// ---------------------------------------------------------------------------
extern "C" void kernel_launch(void* const* d_in, const int* in_sizes, int n_in,
                              void* d_out, int out_size)
{
    const float* x   = (const float*)d_in[0];   // [1,2048,2048]
    const float* w   = (const float*)d_in[1];   // [4,2048,2048]
    const float* ve  = (const float*)d_in[2];   // [1,2048,2048]
    const float* lam = (const float*)d_in[3];   // [2]
    float* out = (float*)d_out;                 // [1,2048,2048] f32

    float *qkv_ptr = nullptr, *y_ptr = nullptr, *wr_ptr = nullptr, *xr_ptr = nullptr;
    cudaGetSymbolAddress((void**)&qkv_ptr, g_qkv);
    cudaGetSymbolAddress((void**)&y_ptr,   g_y);
    cudaGetSymbolAddress((void**)&wr_ptr,  g_wr);
    cudaGetSymbolAddress((void**)&xr_ptr,  g_xr);

    // 0) pre-round x, w to tf32
    round_tf32_kernel<<<2048, 256>>>((const float4*)x, (float4*)xr_ptr,
                                     T_SEQ * DIM_C / 4);
    round_tf32_kernel<<<4096, 256>>>((const float4*)w, (float4*)wr_ptr,
                                     4 * DIM_C * DIM_C / 4);

    const int gemm_smem = GSTAGES * 2 * GBUF * (int)sizeof(float);   // 110,592 B
    cudaFuncSetAttribute(gemm_tf32_kernel,
                         cudaFuncAttributeMaxDynamicSharedMemorySize, gemm_smem);

    // 1) QKV projection
    gemm_tf32_kernel<<<dim3(48, 16), 256, gemm_smem>>>(xr_ptr, wr_ptr, qkv_ptr,
                                                       2048, 6144, 2048);

    // 2) RMSNorm + RoPE + v blend (writes tf32-rounded q/k/v)
    postproc_kernel<<<dim3(2048, 16), 128>>>(ve, lam);

    // 3) causal attention (writes tf32-rounded y)
    cudaFuncSetAttribute(attn_kernel,
                         cudaFuncAttributeMaxDynamicSharedMemorySize, ATTN_SMEM);
    attn_kernel<<<dim3(32, 16), 256, ATTN_SMEM>>>();

    // 4) output projection
    gemm_tf32_kernel<<<dim3(16, 16), 256, gemm_smem>>>(
        y_ptr, wr_ptr + (size_t)3 * DIM_C * DIM_C, out, 2048, 2048, 2048);
}

// round 10
// speedup vs baseline: 1.5817x; 1.0155x over previous
#include <cuda_runtime.h>
#include <math.h>
#include <stdint.h>

#define T_SEQ  2048
#define DIM_C  2048
#define NH     16
#define HD     128
#define QKV_N  6144      // 3 * 2048, row layout [t][e*2048 + h*128 + d]
#define ATTN_SCALE 0.12f

// Scratch
__device__ float g_qkv[(size_t)T_SEQ * QKV_N];        // 50 MB
__device__ float g_y[(size_t)T_SEQ * DIM_C];          // 16 MB
__device__ float g_wr[(size_t)4 * DIM_C * DIM_C];     // 64 MB (tf32-rounded w)
__device__ float g_xr[(size_t)T_SEQ * DIM_C];         // 16 MB (tf32-rounded x)

// ---------------------------------------------------------------------------
// helpers
// ---------------------------------------------------------------------------
__device__ __forceinline__ float tf32r(float x) {
    unsigned u;
    asm("cvt.rna.tf32.f32 %0, %1;" : "=r"(u) : "f"(x));
    return __uint_as_float(u);
}

__device__ __forceinline__ void mma_tf32(float* d, const float* a, const float* b) {
    asm volatile(
        "mma.sync.aligned.m16n8k8.row.col.f32.tf32.tf32.f32 "
        "{%0,%1,%2,%3}, {%4,%5,%6,%7}, {%8,%9}, {%0,%1,%2,%3};\n"
        : "+f"(d[0]), "+f"(d[1]), "+f"(d[2]), "+f"(d[3])
        : "r"(__float_as_uint(a[0])), "r"(__float_as_uint(a[1])),
          "r"(__float_as_uint(a[2])), "r"(__float_as_uint(a[3])),
          "r"(__float_as_uint(b[0])), "r"(__float_as_uint(b[1])));
}

__device__ __forceinline__ unsigned smem_u32(const void* p) {
    return (unsigned)__cvta_generic_to_shared(p);
}

__device__ __forceinline__ void ldsm4(float* r, unsigned addr) {
    unsigned* u = (unsigned*)r;
    asm volatile("ldmatrix.sync.aligned.m8n8.x4.shared.b16 {%0,%1,%2,%3}, [%4];"
                 : "=r"(u[0]), "=r"(u[1]), "=r"(u[2]), "=r"(u[3]) : "r"(addr));
}

#define CP16(dst, src) \
    asm volatile("cp.async.cg.shared.global [%0], [%1], 16;" :: "r"(dst), "l"(src))
#define CPCOMMIT() asm volatile("cp.async.commit_group;")
#define CPWAIT1()  asm volatile("cp.async.wait_group 1;" ::: "memory")
#define CPWAIT0()  asm volatile("cp.async.wait_group 0;" ::: "memory")

// ---------------------------------------------------------------------------
// tf32 rounding pass (x, w -> scratch, once)
// ---------------------------------------------------------------------------
__global__ void round_tf32_kernel(const float4* __restrict__ src,
                                  float4* __restrict__ dst, int n4)
{
    for (int i = blockIdx.x * blockDim.x + threadIdx.x; i < n4;
         i += gridDim.x * blockDim.x) {
        float4 v = src[i];
        dst[i] = make_float4(tf32r(v.x), tf32r(v.y), tf32r(v.z), tf32r(v.w));
    }
}

// ---------------------------------------------------------------------------
// GEMM (TN): C[m][n] = sum_k A[m*K+k] * B[n*K+k].  Inputs pre-rounded tf32.
// 128x128 tile, BK=32, 8 warps (2x4), warp tile 64x32.
// 3-stage cp.async ring, one __syncthreads per k-iter, paired-B ldmatrix.x4.
// fuse==1 (QKV): tile covers one (e, head) x 128 rows; epilogue does
// RMSNorm + RoPE (e<2) / v-blend (e==2) in-smem and writes tf32 q/k/v.
// ---------------------------------------------------------------------------
#define GSPAD   36
#define GBUF    (128 * GSPAD)
#define GSTAGES 3

__global__ __launch_bounds__(256, 2)
void gemm_tf32_kernel(const float* __restrict__ A,
                      const float* __restrict__ B,
                      float* __restrict__ C,
                      int M, int N, int K, int fuse,
                      const float* __restrict__ ve,
                      const float* __restrict__ lam)
{
    extern __shared__ float smg[];
    float* As = smg;                         // [3][128][36]
    float* Bs = smg + GSTAGES * GBUF;        // [3][128][36]

    const int tid  = threadIdx.x;
    const int lane = tid & 31;
    const int wid  = tid >> 5;
    const int g    = lane >> 2;
    const int tig  = lane & 3;
    const int wm   = (wid & 1) * 64;
    const int wn   = (wid >> 1) * 32;

    const int rowBase = blockIdx.y * 128;
    const int colBase = blockIdx.x * 128;
    const float* Ag = A + (size_t)rowBase * K;
    const float* Bg = B + (size_t)colBase * K;

    const int r0 = tid >> 3;
    const int c4 = (tid & 7) << 2;

    // ldmatrix lane addressing
    const int arow = (lane & 7) + ((lane >> 3) & 1) * 8;
    const int acol = (lane >> 4) * 4;
    const int tl   = lane >> 3;                    // tile index 0..3
    const int brow = (lane & 7) + (tl >> 1) * 8;   // tiles 2,3 -> +8 rows
    const int bcol = (tl & 1) * 4;                 // tiles 1,3 -> k+4

    unsigned aAddr[4], bAddr[2];
#pragma unroll
    for (int mi = 0; mi < 4; mi++)
        aAddr[mi] = smem_u32(&As[(wm + mi * 16 + arow) * GSPAD + acol]);
#pragma unroll
    for (int p = 0; p < 2; p++)
        bAddr[p] = smem_u32(&Bs[(wn + p * 16 + brow) * GSPAD + bcol]);

    const unsigned asA = smem_u32(As);
    const unsigned asB = smem_u32(Bs);
    const unsigned STGB = GBUF * 4;
    const unsigned dstOff = (unsigned)((r0 * GSPAD + c4) * 4);

    float acc[4][4][4];
#pragma unroll
    for (int mi = 0; mi < 4; mi++)
#pragma unroll
        for (int ni = 0; ni < 4; ni++)
#pragma unroll
            for (int c = 0; c < 4; c++) acc[mi][ni][c] = 0.0f;

    const int nk = K >> 5;

    // prologue: stages 0,1
#pragma unroll
    for (int s = 0; s < GSTAGES - 1; s++) {
        const unsigned so = s * STGB;
        const int k0 = s << 5;
#pragma unroll
        for (int i = 0; i < 4; i++) {
            int r = r0 + 32 * i;
            CP16(asA + so + dstOff + (unsigned)(i * 32 * GSPAD * 4),
                 Ag + (size_t)r * K + k0 + c4);
            CP16(asB + so + dstOff + (unsigned)(i * 32 * GSPAD * 4),
                 Bg + (size_t)r * K + k0 + c4);
        }
        CPCOMMIT();
    }

    int slot = 0;
    for (int kt = 0; kt < nk; kt++) {
        CPWAIT1();
        __syncthreads();

        if (kt + GSTAGES - 1 < nk) {
            const int ks = kt + GSTAGES - 1;
            const unsigned so = (unsigned)(ks % GSTAGES) * STGB;
            const int k0 = ks << 5;
#pragma unroll
            for (int i = 0; i < 4; i++) {
                int r = r0 + 32 * i;
                CP16(asA + so + dstOff + (unsigned)(i * 32 * GSPAD * 4),
                     Ag + (size_t)r * K + k0 + c4);
                CP16(asB + so + dstOff + (unsigned)(i * 32 * GSPAD * 4),
                     Bg + (size_t)r * K + k0 + c4);
            }
        }
        CPCOMMIT();

        const unsigned cOff = (unsigned)slot * STGB;
#pragma unroll
        for (int ks = 0; ks < 4; ks++) {
            const unsigned kOff = cOff + ks * 32;
            float a[4][4], bq[2][4];
#pragma unroll
            for (int mi = 0; mi < 4; mi++) ldsm4(a[mi], aAddr[mi] + kOff);
#pragma unroll
            for (int p = 0; p < 2; p++) ldsm4(bq[p], bAddr[p] + kOff);
#pragma unroll
            for (int mi = 0; mi < 4; mi++)
#pragma unroll
                for (int p = 0; p < 2; p++) {
                    mma_tf32(acc[mi][2 * p],     a[mi], &bq[p][0]);
                    mma_tf32(acc[mi][2 * p + 1], a[mi], &bq[p][2]);
                }
        }
        slot = (slot + 1 == GSTAGES) ? 0 : slot + 1;
    }

    if (!fuse) {
        // plain epilogue (output projection)
        float* Cp = C + (size_t)rowBase * N + colBase;
#pragma unroll
        for (int mi = 0; mi < 4; mi++) {
            int m = wm + mi * 16 + g;
#pragma unroll
            for (int ni = 0; ni < 4; ni++) {
                int n = wn + ni * 8 + tig * 2;
                *(float2*)&Cp[(size_t)m * N + n] =
                    make_float2(acc[mi][ni][0], acc[mi][ni][1]);
                *(float2*)&Cp[(size_t)(m + 8) * N + n] =
                    make_float2(acc[mi][ni][2], acc[mi][ni][3]);
            }
        }
        return;
    }

    // ---- fused epilogue: RMSNorm + RoPE / v-blend on the tile in smem ----
    __syncthreads();                 // all warps done with ldsm of last chunk
    float* Cs = smg;                 // [128][132] = 67,584 B (fits in ring)
#pragma unroll
    for (int mi = 0; mi < 4; mi++) {
        int m = wm + mi * 16 + g;
#pragma unroll
        for (int ni = 0; ni < 4; ni++) {
            int n = wn + ni * 8 + tig * 2;
            *(float2*)&Cs[m * 132 + n] =
                make_float2(acc[mi][ni][0], acc[mi][ni][1]);
            *(float2*)&Cs[(m + 8) * 132 + n] =
                make_float2(acc[mi][ni][2], acc[mi][ni][3]);
        }
    }
    __syncthreads();

    const int e = colBase >> 11;               // 0=q 1=k 2=v
    const float lam0 = (e == 2) ? lam[0] : 0.0f;
    const float lam1 = (e == 2) ? lam[1] : 0.0f;

    for (int rr = 0; rr < 16; rr++) {
        const int r = wid * 16 + rr;
        const int t = rowBase + r;
        float4 v = *(const float4*)&Cs[r * 132 + lane * 4];
        float ss = v.x * v.x + v.y * v.y + v.z * v.z + v.w * v.w;
#pragma unroll
        for (int o = 16; o > 0; o >>= 1)
            ss += __shfl_xor_sync(0xffffffffu, ss, o);
        const float rinv = rsqrtf(ss * (1.0f / 128.0f) + 1e-6f);

        float o4[4];
        const float* vp = (const float*)&v;
        if (e < 2) {
#pragma unroll
            for (int q = 0; q < 4; q++) {
                int c = lane * 4 + q;
                int j = c & 63;
                float cur = vp[q] * rinv;
                float par = Cs[r * 132 + (c ^ 64)] * rinv;
                float cs, sn;
                if (j < 32) {
                    float fr = exp2f((-10.0f / 31.0f) * (float)j);
                    float th = (float)t * fr;
                    cs = cosf(th); sn = sinf(th);
                } else { cs = 1.0f; sn = 0.0f; }
                o4[q] = (c < 64) ? (cur * cs + par * sn) : (cur * cs - par * sn);
            }
        } else {
            float4 vv = *(const float4*)(ve + (size_t)t * DIM_C +
                                         (colBase & 2047) + lane * 4);
            const float* vvp = (const float*)&vv;
#pragma unroll
            for (int q = 0; q < 4; q++)
                o4[q] = lam0 * (vp[q] * rinv) + lam1 * vvp[q];
        }
        *(float4*)&C[(size_t)t * N + colBase + lane * 4] =
            make_float4(tf32r(o4[0]), tf32r(o4[1]), tf32r(o4[2]), tf32r(o4[3]));
    }
}

// ---------------------------------------------------------------------------
// Causal flash attention (tf32 mma + paired ldmatrix.x4). Q-tile 64, KV 64.
// (unchanged from R8 — proven at rel_err 7.16e-4)
// ---------------------------------------------------------------------------
#define AQ_OFF   0
#define AKU_OFF  (64 * 132)
#define AV_OFF   (AKU_OFF + 64 * 132)
#define ARM_OFF  (AV_OFF + 128 * 68)
#define ARS_OFF  (ARM_OFF + 128)
#define ATTN_SMEM ((ARS_OFF + 128) * 4)     // 103,424 B

__global__ __launch_bounds__(256, 2)
void attn_kernel()
{
    extern __shared__ float sm[];
    float* Qs    = sm + AQ_OFF;
    float* Ks    = sm + AKU_OFF;
    float* Ps    = sm + AKU_OFF;   // alias
    float* Vst   = sm + AV_OFF;
    float* rpmax = sm + ARM_OFF;
    float* rpsum = sm + ARS_OFF;

    const int h     = blockIdx.y;
    const int qt    = 31 - (int)blockIdx.x;
    const int qbase = qt * 64;
    const int tid   = threadIdx.x;
    const int lane  = tid & 31;
    const int wid   = tid >> 5;
    const int g     = lane >> 2;
    const int tig   = lane & 3;
    const int rw    = (wid & 3) * 16;
    const int ch    = wid >> 2;

    const int arow = (lane & 7) + ((lane >> 3) & 1) * 8;
    const int acol = (lane >> 4) * 4;
    const int tl   = lane >> 3;
    const int brow = (lane & 7) + (tl >> 1) * 8;
    const int bcol = (tl & 1) * 4;

    const unsigned qAddr = smem_u32(&Qs[(rw + arow) * 132 + acol]);
    const unsigned pAddr = smem_u32(&Ps[(rw + arow) * 68 + acol]);
    unsigned kAddr[2], vAddr[4];
#pragma unroll
    for (int p = 0; p < 2; p++)
        kAddr[p] = smem_u32(&Ks[(ch * 32 + p * 16 + brow) * 132 + bcol]);
#pragma unroll
    for (int p = 0; p < 4; p++)
        vAddr[p] = smem_u32(&Vst[(ch * 64 + p * 16 + brow) * 68 + bcol]);

    const unsigned ksBase = smem_u32(Ks);

    const float* qg = g_qkv + (size_t)qbase * QKV_N + h * HD;
#pragma unroll
    for (int f = tid; f < 64 * 32; f += 256) {
        int r = f >> 5, d4 = (f & 31) << 2;
        *(float4*)&Qs[r * 132 + d4] = *(const float4*)(qg + (size_t)r * QKV_N + d4);
    }

    float oacc[8][4];
#pragma unroll
    for (int nd = 0; nd < 8; nd++)
#pragma unroll
        for (int c = 0; c < 4; c++) oacc[nd][c] = 0.0f;

    float m0 = -INFINITY, m1 = -INFINITY, l0 = 0.0f, l1 = 0.0f;

    const int row0 = qbase + rw + g;
    const int row1 = row0 + 8;

    __syncthreads();

    for (int kb = 0; kb <= qt; kb++) {
        const float* kg = g_qkv + (size_t)(kb * 64) * QKV_N + 2048 + h * HD;
#pragma unroll
        for (int f = tid; f < 64 * 32; f += 256) {
            int c = f >> 5, d4 = (f & 31) << 2;
            CP16(ksBase + (unsigned)((c * 132 + d4) * 4),
                 kg + (size_t)c * QKV_N + d4);
        }
        CPCOMMIT();
        const float* vg = g_qkv + (size_t)(kb * 64) * QKV_N + 4096 + h * HD;
#pragma unroll
        for (int f = tid; f < 64 * 32; f += 256) {
            int d4 = (f >> 6) << 2, c = f & 63;
            float4 v = *(const float4*)(vg + (size_t)c * QKV_N + d4);
            Vst[(d4 + 0) * 68 + c] = v.x;
            Vst[(d4 + 1) * 68 + c] = v.y;
            Vst[(d4 + 2) * 68 + c] = v.z;
            Vst[(d4 + 3) * 68 + c] = v.w;
        }
        CPWAIT0();
        __syncthreads();   // B1

        float sacc[4][4];
#pragma unroll
        for (int ni = 0; ni < 4; ni++)
#pragma unroll
            for (int c = 0; c < 4; c++) sacc[ni][c] = 0.0f;

#pragma unroll
        for (int kk = 0; kk < 16; kk++) {
            float a[4], bq[2][4];
            ldsm4(a, qAddr + kk * 32);
#pragma unroll
            for (int p = 0; p < 2; p++) {
                ldsm4(bq[p], kAddr[p] + kk * 32);
                mma_tf32(sacc[2 * p],     a, &bq[p][0]);
                mma_tf32(sacc[2 * p + 1], a, &bq[p][2]);
            }
        }

        const int cbase = kb * 64 + ch * 32;
        const bool needmask = (kb == qt);
        float rmax0 = -INFINITY, rmax1 = -INFINITY;
#pragma unroll
        for (int ni = 0; ni < 4; ni++) {
            int c0 = cbase + ni * 8 + 2 * tig;
            float v0 = sacc[ni][0] * ATTN_SCALE;
            float v1 = sacc[ni][1] * ATTN_SCALE;
            float v2 = sacc[ni][2] * ATTN_SCALE;
            float v3 = sacc[ni][3] * ATTN_SCALE;
            if (needmask) {
                if (c0     > row0) v0 = -INFINITY;
                if (c0 + 1 > row0) v1 = -INFINITY;
                if (c0     > row1) v2 = -INFINITY;
                if (c0 + 1 > row1) v3 = -INFINITY;
            }
            sacc[ni][0] = v0; sacc[ni][1] = v1;
            sacc[ni][2] = v2; sacc[ni][3] = v3;
            rmax0 = fmaxf(rmax0, fmaxf(v0, v1));
            rmax1 = fmaxf(rmax1, fmaxf(v2, v3));
        }
        rmax0 = fmaxf(rmax0, __shfl_xor_sync(0xffffffffu, rmax0, 1));
        rmax0 = fmaxf(rmax0, __shfl_xor_sync(0xffffffffu, rmax0, 2));
        rmax1 = fmaxf(rmax1, __shfl_xor_sync(0xffffffffu, rmax1, 1));
        rmax1 = fmaxf(rmax1, __shfl_xor_sync(0xffffffffu, rmax1, 2));
        if (tig == 0) {
            rpmax[(rw + g) * 2 + ch]     = rmax0;
            rpmax[(rw + g + 8) * 2 + ch] = rmax1;
        }
        __syncthreads();   // B2

        float mt0 = fmaxf(rpmax[(rw + g) * 2],     rpmax[(rw + g) * 2 + 1]);
        float mt1 = fmaxf(rpmax[(rw + g + 8) * 2], rpmax[(rw + g + 8) * 2 + 1]);
        float mn0 = fmaxf(m0, mt0);
        float mn1 = fmaxf(m1, mt1);
        float fr0 = __expf(m0 - mn0);
        float fr1 = __expf(m1 - mn1);
        m0 = mn0; m1 = mn1;

        float sum0 = 0.0f, sum1 = 0.0f;
#pragma unroll
        for (int ni = 0; ni < 4; ni++) {
            float p0 = __expf(sacc[ni][0] - mn0);
            float p1 = __expf(sacc[ni][1] - mn0);
            float p2 = __expf(sacc[ni][2] - mn1);
            float p3 = __expf(sacc[ni][3] - mn1);
            sum0 += p0 + p1;
            sum1 += p2 + p3;
            int cc = ch * 32 + ni * 8 + 2 * tig;
            *(float2*)&Ps[(rw + g) * 68 + cc]     = make_float2(tf32r(p0), tf32r(p1));
            *(float2*)&Ps[(rw + g + 8) * 68 + cc] = make_float2(tf32r(p2), tf32r(p3));
        }
        sum0 += __shfl_xor_sync(0xffffffffu, sum0, 1);
        sum0 += __shfl_xor_sync(0xffffffffu, sum0, 2);
        sum1 += __shfl_xor_sync(0xffffffffu, sum1, 1);
        sum1 += __shfl_xor_sync(0xffffffffu, sum1, 2);
        l0 = l0 * fr0 + sum0;
        l1 = l1 * fr1 + sum1;
        __syncthreads();   // B3 (P read spans both col halves)

#pragma unroll
        for (int nd = 0; nd < 8; nd++) {
            oacc[nd][0] *= fr0; oacc[nd][1] *= fr0;
            oacc[nd][2] *= fr1; oacc[nd][3] *= fr1;
        }

#pragma unroll
        for (int ss = 0; ss < 8; ss++) {
            float a[4], bq[4];
            ldsm4(a, pAddr + ss * 32);
#pragma unroll
            for (int p = 0; p < 4; p++) {
                ldsm4(bq, vAddr[p] + ss * 32);
                mma_tf32(oacc[2 * p],     a, &bq[0]);
                mma_tf32(oacc[2 * p + 1], a, &bq[2]);
            }
        }
        __syncthreads();   // B4
    }

    if (tig == 0) {
        rpsum[(rw + g) * 2 + ch]     = l0;
        rpsum[(rw + g + 8) * 2 + ch] = l1;
    }
    __syncthreads();
    const float lt0 = rpsum[(rw + g) * 2]     + rpsum[(rw + g) * 2 + 1];
    const float lt1 = rpsum[(rw + g + 8) * 2] + rpsum[(rw + g + 8) * 2 + 1];
    const float inv0 = 1.0f / lt0;
    const float inv1 = 1.0f / lt1;
    float* dst0 = g_y + (size_t)row0 * DIM_C + h * HD + ch * 64;
    float* dst1 = g_y + (size_t)row1 * DIM_C + h * HD + ch * 64;
#pragma unroll
    for (int nd = 0; nd < 8; nd++) {
        int col = nd * 8 + 2 * tig;
        *(float2*)&dst0[col] =
            make_float2(tf32r(oacc[nd][0] * inv0), tf32r(oacc[nd][1] * inv0));
        *(float2*)&dst1[col] =
            make_float2(tf32r(oacc[nd][2] * inv1), tf32r(oacc[nd][3] * inv1));
    }
}

// ---------------------------------------------------------------------------
extern "C" void kernel_launch(void* const* d_in, const int* in_sizes, int n_in,
                              void* d_out, int out_size)
{
    const float* x   = (const float*)d_in[0];   // [1,2048,2048]
    const float* w   = (const float*)d_in[1];   // [4,2048,2048]
    const float* ve  = (const float*)d_in[2];   // [1,2048,2048]
    const float* lam = (const float*)d_in[3];   // [2]
    float* out = (float*)d_out;                 // [1,2048,2048] f32

    float *qkv_ptr = nullptr, *y_ptr = nullptr, *wr_ptr = nullptr, *xr_ptr = nullptr;
    cudaGetSymbolAddress((void**)&qkv_ptr, g_qkv);
    cudaGetSymbolAddress((void**)&y_ptr,   g_y);
    cudaGetSymbolAddress((void**)&wr_ptr,  g_wr);
    cudaGetSymbolAddress((void**)&xr_ptr,  g_xr);

    // 0) pre-round x, w to tf32
    round_tf32_kernel<<<2048, 256>>>((const float4*)x, (float4*)xr_ptr,
                                     T_SEQ * DIM_C / 4);
    round_tf32_kernel<<<4096, 256>>>((const float4*)w, (float4*)wr_ptr,
                                     4 * DIM_C * DIM_C / 4);

    const int gemm_smem = GSTAGES * 2 * GBUF * (int)sizeof(float);   // 110,592 B
    cudaFuncSetAttribute(gemm_tf32_kernel,
                         cudaFuncAttributeMaxDynamicSharedMemorySize, gemm_smem);

    // 1) QKV projection + fused RMSNorm/RoPE/v-blend -> g_qkv (tf32-rounded)
    gemm_tf32_kernel<<<dim3(48, 16), 256, gemm_smem>>>(
        xr_ptr, wr_ptr, qkv_ptr, 2048, 6144, 2048, 1, ve, lam);

    // 2) causal attention (writes tf32-rounded y)
    cudaFuncSetAttribute(attn_kernel,
                         cudaFuncAttributeMaxDynamicSharedMemorySize, ATTN_SMEM);
    attn_kernel<<<dim3(32, 16), 256, ATTN_SMEM>>>();

    // 3) output projection
    gemm_tf32_kernel<<<dim3(16, 16), 256, gemm_smem>>>(
        y_ptr, wr_ptr + (size_t)3 * DIM_C * DIM_C, out, 2048, 2048, 2048,
        0, nullptr, nullptr);
}

// round 15
// speedup vs baseline: 1.6455x; 1.0403x over previous
#include <cuda_runtime.h>
#include <math.h>
#include <stdint.h>

#define T_SEQ  2048
#define DIM_C  2048
#define NH     16
#define HD     128
#define QKV_N  6144      // 3 * 2048, row layout [t][e*2048 + h*128 + d]
#define ATTN_SCALE 0.12f

// Scratch
__device__ float g_qkv[(size_t)T_SEQ * QKV_N];        // 50 MB
__device__ float g_y[(size_t)T_SEQ * DIM_C];          // 16 MB
__device__ float g_wr[(size_t)4 * DIM_C * DIM_C];     // 64 MB (tf32-rounded w)
__device__ float g_xr[(size_t)T_SEQ * DIM_C];         // 16 MB (tf32-rounded x)

// ---------------------------------------------------------------------------
// helpers
// ---------------------------------------------------------------------------
__device__ __forceinline__ float tf32r(float x) {
    unsigned u;
    asm("cvt.rna.tf32.f32 %0, %1;" : "=r"(u) : "f"(x));
    return __uint_as_float(u);
}

__device__ __forceinline__ void mma_tf32(float* d, const float* a, const float* b) {
    asm volatile(
        "mma.sync.aligned.m16n8k8.row.col.f32.tf32.tf32.f32 "
        "{%0,%1,%2,%3}, {%4,%5,%6,%7}, {%8,%9}, {%0,%1,%2,%3};\n"
        : "+f"(d[0]), "+f"(d[1]), "+f"(d[2]), "+f"(d[3])
        : "r"(__float_as_uint(a[0])), "r"(__float_as_uint(a[1])),
          "r"(__float_as_uint(a[2])), "r"(__float_as_uint(a[3])),
          "r"(__float_as_uint(b[0])), "r"(__float_as_uint(b[1])));
}

__device__ __forceinline__ unsigned smem_u32(const void* p) {
    return (unsigned)__cvta_generic_to_shared(p);
}

__device__ __forceinline__ void ldsm4(float* r, unsigned addr) {
    unsigned* u = (unsigned*)r;
    asm volatile("ldmatrix.sync.aligned.m8n8.x4.shared.b16 {%0,%1,%2,%3}, [%4];"
                 : "=r"(u[0]), "=r"(u[1]), "=r"(u[2]), "=r"(u[3]) : "r"(addr));
}

#define CP16(dst, src) \
    asm volatile("cp.async.cg.shared.global [%0], [%1], 16;" :: "r"(dst), "l"(src))
#define CPCOMMIT() asm volatile("cp.async.commit_group;")
#define CPWAIT1()  asm volatile("cp.async.wait_group 1;" ::: "memory")
#define CPWAIT0()  asm volatile("cp.async.wait_group 0;" ::: "memory")

// ---------------------------------------------------------------------------
// tf32 rounding pass (x, w -> scratch, once)
// ---------------------------------------------------------------------------
__global__ void round_tf32_kernel(const float4* __restrict__ src,
                                  float4* __restrict__ dst, int n4)
{
    for (int i = blockIdx.x * blockDim.x + threadIdx.x; i < n4;
         i += gridDim.x * blockDim.x) {
        float4 v = src[i];
        dst[i] = make_float4(tf32r(v.x), tf32r(v.y), tf32r(v.z), tf32r(v.w));
    }
}

// ---------------------------------------------------------------------------
// GEMM (TN): unchanged (proven through R10).
// ---------------------------------------------------------------------------
#define GSPAD   36
#define GBUF    (128 * GSPAD)
#define GSTAGES 3

__global__ __launch_bounds__(256, 2)
void gemm_tf32_kernel(const float* __restrict__ A,
                      const float* __restrict__ B,
                      float* __restrict__ C,
                      int M, int N, int K, int fuse,
                      const float* __restrict__ ve,
                      const float* __restrict__ lam)
{
    extern __shared__ float smg[];
    float* As = smg;                         // [3][128][36]
    float* Bs = smg + GSTAGES * GBUF;        // [3][128][36]

    const int tid  = threadIdx.x;
    const int lane = tid & 31;
    const int wid  = tid >> 5;
    const int g    = lane >> 2;
    const int tig  = lane & 3;
    const int wm   = (wid & 1) * 64;
    const int wn   = (wid >> 1) * 32;

    const int rowBase = blockIdx.y * 128;
    const int colBase = blockIdx.x * 128;
    const float* Ag = A + (size_t)rowBase * K;
    const float* Bg = B + (size_t)colBase * K;

    const int r0 = tid >> 3;
    const int c4 = (tid & 7) << 2;

    const int arow = (lane & 7) + ((lane >> 3) & 1) * 8;
    const int acol = (lane >> 4) * 4;
    const int tl   = lane >> 3;
    const int brow = (lane & 7) + (tl >> 1) * 8;
    const int bcol = (tl & 1) * 4;

    unsigned aAddr[4], bAddr[2];
#pragma unroll
    for (int mi = 0; mi < 4; mi++)
        aAddr[mi] = smem_u32(&As[(wm + mi * 16 + arow) * GSPAD + acol]);
#pragma unroll
    for (int p = 0; p < 2; p++)
        bAddr[p] = smem_u32(&Bs[(wn + p * 16 + brow) * GSPAD + bcol]);

    const unsigned asA = smem_u32(As);
    const unsigned asB = smem_u32(Bs);
    const unsigned STGB = GBUF * 4;
    const unsigned dstOff = (unsigned)((r0 * GSPAD + c4) * 4);

    float acc[4][4][4];
#pragma unroll
    for (int mi = 0; mi < 4; mi++)
#pragma unroll
        for (int ni = 0; ni < 4; ni++)
#pragma unroll
            for (int c = 0; c < 4; c++) acc[mi][ni][c] = 0.0f;

    const int nk = K >> 5;

#pragma unroll
    for (int s = 0; s < GSTAGES - 1; s++) {
        const unsigned so = s * STGB;
        const int k0 = s << 5;
#pragma unroll
        for (int i = 0; i < 4; i++) {
            int r = r0 + 32 * i;
            CP16(asA + so + dstOff + (unsigned)(i * 32 * GSPAD * 4),
                 Ag + (size_t)r * K + k0 + c4);
            CP16(asB + so + dstOff + (unsigned)(i * 32 * GSPAD * 4),
                 Bg + (size_t)r * K + k0 + c4);
        }
        CPCOMMIT();
    }

    int slot = 0;
    for (int kt = 0; kt < nk; kt++) {
        CPWAIT1();
        __syncthreads();

        if (kt + GSTAGES - 1 < nk) {
            const int ks = kt + GSTAGES - 1;
            const unsigned so = (unsigned)(ks % GSTAGES) * STGB;
            const int k0 = ks << 5;
#pragma unroll
            for (int i = 0; i < 4; i++) {
                int r = r0 + 32 * i;
                CP16(asA + so + dstOff + (unsigned)(i * 32 * GSPAD * 4),
                     Ag + (size_t)r * K + k0 + c4);
                CP16(asB + so + dstOff + (unsigned)(i * 32 * GSPAD * 4),
                     Bg + (size_t)r * K + k0 + c4);
            }
        }
        CPCOMMIT();

        const unsigned cOff = (unsigned)slot * STGB;
#pragma unroll
        for (int ks = 0; ks < 4; ks++) {
            const unsigned kOff = cOff + ks * 32;
            float a[4][4], bq[2][4];
#pragma unroll
            for (int mi = 0; mi < 4; mi++) ldsm4(a[mi], aAddr[mi] + kOff);
#pragma unroll
            for (int p = 0; p < 2; p++) ldsm4(bq[p], bAddr[p] + kOff);
#pragma unroll
            for (int mi = 0; mi < 4; mi++)
#pragma unroll
                for (int p = 0; p < 2; p++) {
                    mma_tf32(acc[mi][2 * p],     a[mi], &bq[p][0]);
                    mma_tf32(acc[mi][2 * p + 1], a[mi], &bq[p][2]);
                }
        }
        slot = (slot + 1 == GSTAGES) ? 0 : slot + 1;
    }

    if (!fuse) {
        float* Cp = C + (size_t)rowBase * N + colBase;
#pragma unroll
        for (int mi = 0; mi < 4; mi++) {
            int m = wm + mi * 16 + g;
#pragma unroll
            for (int ni = 0; ni < 4; ni++) {
                int n = wn + ni * 8 + tig * 2;
                *(float2*)&Cp[(size_t)m * N + n] =
                    make_float2(acc[mi][ni][0], acc[mi][ni][1]);
                *(float2*)&Cp[(size_t)(m + 8) * N + n] =
                    make_float2(acc[mi][ni][2], acc[mi][ni][3]);
            }
        }
        return;
    }

    // fused epilogue: RMSNorm + RoPE / v-blend (proven in R10)
    __syncthreads();
    float* Cs = smg;                 // [128][132]
#pragma unroll
    for (int mi = 0; mi < 4; mi++) {
        int m = wm + mi * 16 + g;
#pragma unroll
        for (int ni = 0; ni < 4; ni++) {
            int n = wn + ni * 8 + tig * 2;
            *(float2*)&Cs[m * 132 + n] =
                make_float2(acc[mi][ni][0], acc[mi][ni][1]);
            *(float2*)&Cs[(m + 8) * 132 + n] =
                make_float2(acc[mi][ni][2], acc[mi][ni][3]);
        }
    }
    __syncthreads();

    const int e = colBase >> 11;               // 0=q 1=k 2=v
    const float lam0 = (e == 2) ? lam[0] : 0.0f;
    const float lam1 = (e == 2) ? lam[1] : 0.0f;

    for (int rr = 0; rr < 16; rr++) {
        const int r = wid * 16 + rr;
        const int t = rowBase + r;
        float4 v = *(const float4*)&Cs[r * 132 + lane * 4];
        float ss = v.x * v.x + v.y * v.y + v.z * v.z + v.w * v.w;
#pragma unroll
        for (int o = 16; o > 0; o >>= 1)
            ss += __shfl_xor_sync(0xffffffffu, ss, o);
        const float rinv = rsqrtf(ss * (1.0f / 128.0f) + 1e-6f);

        float o4[4];
        const float* vp = (const float*)&v;
        if (e < 2) {
#pragma unroll
            for (int q = 0; q < 4; q++) {
                int c = lane * 4 + q;
                int j = c & 63;
                float cur = vp[q] * rinv;
                float par = Cs[r * 132 + (c ^ 64)] * rinv;
                float cs, sn;
                if (j < 32) {
                    float fr = exp2f((-10.0f / 31.0f) * (float)j);
                    float th = (float)t * fr;
                    cs = cosf(th); sn = sinf(th);
                } else { cs = 1.0f; sn = 0.0f; }
                o4[q] = (c < 64) ? (cur * cs + par * sn) : (cur * cs - par * sn);
            }
        } else {
            float4 vv = *(const float4*)(ve + (size_t)t * DIM_C +
                                         (colBase & 2047) + lane * 4);
            const float* vvp = (const float*)&vv;
#pragma unroll
            for (int q = 0; q < 4; q++)
                o4[q] = lam0 * (vp[q] * rinv) + lam1 * vvp[q];
        }
        *(float4*)&C[(size_t)t * N + colBase + lane * 4] =
            make_float4(tf32r(o4[0]), tf32r(o4[1]), tf32r(o4[2]), tf32r(o4[3]));
    }
}

// ---------------------------------------------------------------------------
// Causal flash attention v3 (FIXED K loads): Q-tile 128 (8 warps x 16 rows,
// full 64 kv cols/warp), register-resident P via quad shfl transpose, K/V
// double-buffered, ONE __syncthreads per KV tile. 1 CTA/SM (204.8 KB smem).
// K tile = 64 rows x 512 B -> 2048 CP16 (8 per thread).  [R7-class bug fixed]
// ---------------------------------------------------------------------------
#define KSTR  (64 * 132)
#define VSTR  (128 * 68)
#define AQ3_OFF 0
#define AK3_OFF (128 * 132)
#define AV3_OFF (AK3_OFF + 2 * KSTR)
#define ATTN_SMEM3 ((AV3_OFF + 2 * VSTR) * 4)   // 204,800 B

__global__ __launch_bounds__(256, 1)
void attn_kernel()
{
    extern __shared__ float sm[];
    float* Qs  = sm + AQ3_OFF;
    float* Ks  = sm + AK3_OFF;    // [2][64][132]
    float* Vst = sm + AV3_OFF;    // [2][128][68]

    const int h     = blockIdx.y;
    const int qt    = 15 - (int)blockIdx.x;   // big tiles first
    const int qbase = qt * 128;
    const int tid   = threadIdx.x;
    const int lane  = tid & 31;
    const int wid   = tid >> 5;
    const int g     = lane >> 2;
    const int tig   = lane & 3;
    const int rw    = wid * 16;

    const int arow = (lane & 7) + ((lane >> 3) & 1) * 8;
    const int acol = (lane >> 4) * 4;
    const int tl   = lane >> 3;
    const int brow = (lane & 7) + (tl >> 1) * 8;
    const int bcol = (tl & 1) * 4;

    const unsigned qAddr = smem_u32(&Qs[(rw + arow) * 132 + acol]);
    unsigned kA[2][4], vA[2][8];
#pragma unroll
    for (int b = 0; b < 2; b++) {
#pragma unroll
        for (int p = 0; p < 4; p++)
            kA[b][p] = smem_u32(&Ks[b * KSTR + (p * 16 + brow) * 132 + bcol]);
#pragma unroll
        for (int p = 0; p < 8; p++)
            vA[b][p] = smem_u32(&Vst[b * VSTR + (p * 16 + brow) * 68 + bcol]);
    }
    const unsigned ksB0 = smem_u32(Ks);
    const unsigned ksB1 = smem_u32(Ks + KSTR);

    // load Q tile (128 x 128, already tf32)
    const float* qg = g_qkv + (size_t)qbase * QKV_N + h * HD;
#pragma unroll
    for (int f = tid; f < 128 * 32; f += 256) {
        int r = f >> 5, d4 = (f & 31) << 2;
        *(float4*)&Qs[r * 132 + d4] = *(const float4*)(qg + (size_t)r * QKV_N + d4);
    }

    // initial K0 (cp.async, FULL 32KB: 8 CP16/thread) + V0 (manual transpose)
    {
        const float* kg = g_qkv + 2048 + h * HD;
#pragma unroll
        for (int f = tid; f < 64 * 32; f += 256) {
            int c = f >> 5, seg = (f & 31) << 4;
            CP16(ksB0 + (unsigned)(c * 132 * 4 + seg),
                 (const char*)(kg + (size_t)c * QKV_N) + seg);
        }
        CPCOMMIT();
        const float* vg = g_qkv + 4096 + h * HD;
#pragma unroll
        for (int f = tid; f < 64 * 32; f += 256) {
            int d4 = (f >> 6) << 2, c = f & 63;
            float4 v = *(const float4*)(vg + (size_t)c * QKV_N + d4);
            Vst[(d4 + 0) * 68 + c] = v.x;
            Vst[(d4 + 1) * 68 + c] = v.y;
            Vst[(d4 + 2) * 68 + c] = v.z;
            Vst[(d4 + 3) * 68 + c] = v.w;
        }
    }

    float oacc[16][4];
#pragma unroll
    for (int nd = 0; nd < 16; nd++)
#pragma unroll
        for (int c = 0; c < 4; c++) oacc[nd][c] = 0.0f;

    float m0 = -INFINITY, m1 = -INFINITY, l0 = 0.0f, l1 = 0.0f;
    const int row0 = qbase + rw + g;
    const int row1 = row0 + 8;

    CPWAIT0();
    __syncthreads();

    const int nkv = 2 * qt + 2;
    for (int kb = 0; kb < nkv; kb++) {
        const int buf = kb & 1;
        const bool pre = (kb + 1 < nkv);

        // prefetch next K into other buffer (FULL tile; overlaps compute)
        if (pre) {
            const float* kg = g_qkv + (size_t)((kb + 1) * 64) * QKV_N + 2048 + h * HD;
            const unsigned kd = buf ? ksB0 : ksB1;
#pragma unroll
            for (int f = tid; f < 64 * 32; f += 256) {
                int c = f >> 5, seg = (f & 31) << 4;
                CP16(kd + (unsigned)(c * 132 * 4 + seg),
                     (const char*)(kg + (size_t)c * QKV_N) + seg);
            }
        }
        CPCOMMIT();

        // ---- S = Q K^T : 16 rows x 64 cols per warp ----
        float sacc[8][4];
#pragma unroll
        for (int ni = 0; ni < 8; ni++)
#pragma unroll
            for (int c = 0; c < 4; c++) sacc[ni][c] = 0.0f;

#pragma unroll
        for (int kk = 0; kk < 16; kk++) {
            float a[4], bq[4];
            ldsm4(a, qAddr + kk * 32);
#pragma unroll
            for (int p = 0; p < 4; p++) {
                ldsm4(bq, kA[buf][p] + kk * 32);
                mma_tf32(sacc[2 * p],     a, &bq[0]);
                mma_tf32(sacc[2 * p + 1], a, &bq[2]);
            }
        }

        // prefetch next V into registers (latency covered by softmax + PV)
        float4 vreg[8];
        if (pre) {
            const float* vg = g_qkv + (size_t)((kb + 1) * 64) * QKV_N + 4096 + h * HD;
#pragma unroll
            for (int j = 0; j < 8; j++) {
                int f = tid + 256 * j;
                int d4 = (f >> 6) << 2, c = f & 63;
                vreg[j] = *(const float4*)(vg + (size_t)c * QKV_N + d4);
            }
        }

        // ---- softmax (fully warp-local) ----
        const bool needmask = (kb >= 2 * qt);
        float rmax0 = -INFINITY, rmax1 = -INFINITY;
#pragma unroll
        for (int ni = 0; ni < 8; ni++) {
            int c0 = kb * 64 + ni * 8 + 2 * tig;
            float v0 = sacc[ni][0] * ATTN_SCALE;
            float v1 = sacc[ni][1] * ATTN_SCALE;
            float v2 = sacc[ni][2] * ATTN_SCALE;
            float v3 = sacc[ni][3] * ATTN_SCALE;
            if (needmask) {
                if (c0     > row0) v0 = -INFINITY;
                if (c0 + 1 > row0) v1 = -INFINITY;
                if (c0     > row1) v2 = -INFINITY;
                if (c0 + 1 > row1) v3 = -INFINITY;
            }
            sacc[ni][0] = v0; sacc[ni][1] = v1;
            sacc[ni][2] = v2; sacc[ni][3] = v3;
            rmax0 = fmaxf(rmax0, fmaxf(v0, v1));
            rmax1 = fmaxf(rmax1, fmaxf(v2, v3));
        }
        rmax0 = fmaxf(rmax0, __shfl_xor_sync(0xffffffffu, rmax0, 1));
        rmax0 = fmaxf(rmax0, __shfl_xor_sync(0xffffffffu, rmax0, 2));
        rmax1 = fmaxf(rmax1, __shfl_xor_sync(0xffffffffu, rmax1, 1));
        rmax1 = fmaxf(rmax1, __shfl_xor_sync(0xffffffffu, rmax1, 2));

        float mn0 = fmaxf(m0, rmax0);
        float mn1 = fmaxf(m1, rmax1);
        float fr0 = __expf(m0 - mn0);
        float fr1 = __expf(m1 - mn1);
        m0 = mn0; m1 = mn1;

        float sum0 = 0.0f, sum1 = 0.0f;
#pragma unroll
        for (int ni = 0; ni < 8; ni++) {
            float p0 = __expf(sacc[ni][0] - mn0);
            float p1 = __expf(sacc[ni][1] - mn0);
            float p2 = __expf(sacc[ni][2] - mn1);
            float p3 = __expf(sacc[ni][3] - mn1);
            sum0 += p0 + p1;
            sum1 += p2 + p3;
            sacc[ni][0] = tf32r(p0); sacc[ni][1] = tf32r(p1);
            sacc[ni][2] = tf32r(p2); sacc[ni][3] = tf32r(p3);
        }
        sum0 += __shfl_xor_sync(0xffffffffu, sum0, 1);
        sum0 += __shfl_xor_sync(0xffffffffu, sum0, 2);
        sum1 += __shfl_xor_sync(0xffffffffu, sum1, 1);
        sum1 += __shfl_xor_sync(0xffffffffu, sum1, 2);
        l0 = l0 * fr0 + sum0;
        l1 = l1 * fr1 + sum1;

#pragma unroll
        for (int nd = 0; nd < 16; nd++) {
            oacc[nd][0] *= fr0; oacc[nd][1] *= fr0;
            oacc[nd][2] *= fr1; oacc[nd][3] *= fr1;
        }

        // ---- O += P V : P in regs via quad shfl transpose (C->A layout) ----
        const int src0 = (lane & ~3) | (tig >> 1);
        const int src2 = src0 + 2;
        const bool odd = tig & 1;
#pragma unroll
        for (int sg = 0; sg < 8; sg++) {
            float e0 = __shfl_sync(0xffffffffu, sacc[sg][0], src0);
            float e1 = __shfl_sync(0xffffffffu, sacc[sg][1], src0);
            float e2 = __shfl_sync(0xffffffffu, sacc[sg][2], src0);
            float e3 = __shfl_sync(0xffffffffu, sacc[sg][3], src0);
            float f0 = __shfl_sync(0xffffffffu, sacc[sg][0], src2);
            float f1 = __shfl_sync(0xffffffffu, sacc[sg][1], src2);
            float f2 = __shfl_sync(0xffffffffu, sacc[sg][2], src2);
            float f3 = __shfl_sync(0xffffffffu, sacc[sg][3], src2);
            float a[4];
            a[0] = odd ? e1 : e0;   // P[row g  ][sg*8 + tig]
            a[1] = odd ? e3 : e2;   // P[row g+8][sg*8 + tig]
            a[2] = odd ? f1 : f0;   // P[row g  ][sg*8 + tig+4]
            a[3] = odd ? f3 : f2;   // P[row g+8][sg*8 + tig+4]
#pragma unroll
            for (int p = 0; p < 8; p++) {
                float bq[4];
                ldsm4(bq, vA[buf][p] + sg * 32);
                mma_tf32(oacc[2 * p],     a, &bq[0]);
                mma_tf32(oacc[2 * p + 1], a, &bq[2]);
            }
        }

        // store prefetched V into the other buffer
        if (pre) {
            float* vd = Vst + (buf ? 0 : VSTR);
#pragma unroll
            for (int j = 0; j < 8; j++) {
                int f = tid + 256 * j;
                int d4 = (f >> 6) << 2, c = f & 63;
                vd[(d4 + 0) * 68 + c] = vreg[j].x;
                vd[(d4 + 1) * 68 + c] = vreg[j].y;
                vd[(d4 + 2) * 68 + c] = vreg[j].z;
                vd[(d4 + 3) * 68 + c] = vreg[j].w;
            }
        }
        CPWAIT0();
        __syncthreads();   // single barrier per tile
    }

    // epilogue: normalize, tf32-round
    const float inv0 = 1.0f / l0;
    const float inv1 = 1.0f / l1;
    float* dst0 = g_y + (size_t)row0 * DIM_C + h * HD;
    float* dst1 = g_y + (size_t)row1 * DIM_C + h * HD;
#pragma unroll
    for (int nd = 0; nd < 16; nd++) {
        int col = nd * 8 + 2 * tig;
        *(float2*)&dst0[col] =
            make_float2(tf32r(oacc[nd][0] * inv0), tf32r(oacc[nd][1] * inv0));
        *(float2*)&dst1[col] =
            make_float2(tf32r(oacc[nd][2] * inv1), tf32r(oacc[nd][3] * inv1));
    }
}

// ---------------------------------------------------------------------------
extern "C" void kernel_launch(void* const* d_in, const int* in_sizes, int n_in,
                              void* d_out, int out_size)
{
    const float* x   = (const float*)d_in[0];   // [1,2048,2048]
    const float* w   = (const float*)d_in[1];   // [4,2048,2048]
    const float* ve  = (const float*)d_in[2];   // [1,2048,2048]
    const float* lam = (const float*)d_in[3];   // [2]
    float* out = (float*)d_out;                 // [1,2048,2048] f32

    float *qkv_ptr = nullptr, *y_ptr = nullptr, *wr_ptr = nullptr, *xr_ptr = nullptr;
    cudaGetSymbolAddress((void**)&qkv_ptr, g_qkv);
    cudaGetSymbolAddress((void**)&y_ptr,   g_y);
    cudaGetSymbolAddress((void**)&wr_ptr,  g_wr);
    cudaGetSymbolAddress((void**)&xr_ptr,  g_xr);

    // 0) pre-round x, w to tf32
    round_tf32_kernel<<<2048, 256>>>((const float4*)x, (float4*)xr_ptr,
                                     T_SEQ * DIM_C / 4);
    round_tf32_kernel<<<4096, 256>>>((const float4*)w, (float4*)wr_ptr,
                                     4 * DIM_C * DIM_C / 4);

    const int gemm_smem = GSTAGES * 2 * GBUF * (int)sizeof(float);   // 110,592 B
    cudaFuncSetAttribute(gemm_tf32_kernel,
                         cudaFuncAttributeMaxDynamicSharedMemorySize, gemm_smem);

    // 1) QKV projection + fused RMSNorm/RoPE/v-blend -> g_qkv (tf32-rounded)
    gemm_tf32_kernel<<<dim3(48, 16), 256, gemm_smem>>>(
        xr_ptr, wr_ptr, qkv_ptr, 2048, 6144, 2048, 1, ve, lam);

    // 2) causal attention (writes tf32-rounded y)
    cudaFuncSetAttribute(attn_kernel,
                         cudaFuncAttributeMaxDynamicSharedMemorySize, ATTN_SMEM3);
    attn_kernel<<<dim3(16, 16), 256, ATTN_SMEM3>>>();

    // 3) output projection
    gemm_tf32_kernel<<<dim3(16, 16), 256, gemm_smem>>>(
        y_ptr, wr_ptr + (size_t)3 * DIM_C * DIM_C, out, 2048, 2048, 2048,
        0, nullptr, nullptr);
}

// round 16
// speedup vs baseline: 2.2873x; 1.3901x over previous
#include <cuda_runtime.h>
#include <cuda_fp16.h>
#include <math.h>
#include <stdint.h>

#define T_SEQ  2048
#define DIM_C  2048
#define NH     16
#define HD     128
#define QKV_N  6144      // 3 * 2048, row layout [t][e*2048 + h*128 + d]
#define ATTN_SCALE 0.12f

// Scratch
__device__ float  g_qkv[(size_t)T_SEQ * QKV_N];        // 50 MB (tf32 q/k/v)
__device__ __half g_xh[(size_t)T_SEQ * DIM_C];         // 8 MB
__device__ __half g_wh[(size_t)4 * DIM_C * DIM_C];     // 32 MB
__device__ __half g_yh[(size_t)T_SEQ * DIM_C];         // 8 MB

// ---------------------------------------------------------------------------
// helpers
// ---------------------------------------------------------------------------
__device__ __forceinline__ float tf32r(float x) {
    unsigned u;
    asm("cvt.rna.tf32.f32 %0, %1;" : "=r"(u) : "f"(x));
    return __uint_as_float(u);
}

__device__ __forceinline__ void mma_tf32(float* d, const float* a, const float* b) {
    asm volatile(
        "mma.sync.aligned.m16n8k8.row.col.f32.tf32.tf32.f32 "
        "{%0,%1,%2,%3}, {%4,%5,%6,%7}, {%8,%9}, {%0,%1,%2,%3};\n"
        : "+f"(d[0]), "+f"(d[1]), "+f"(d[2]), "+f"(d[3])
        : "r"(__float_as_uint(a[0])), "r"(__float_as_uint(a[1])),
          "r"(__float_as_uint(a[2])), "r"(__float_as_uint(a[3])),
          "r"(__float_as_uint(b[0])), "r"(__float_as_uint(b[1])));
}

__device__ __forceinline__ void mma_f16(float* d, const unsigned* a, const unsigned* b) {
    asm volatile(
        "mma.sync.aligned.m16n8k16.row.col.f32.f16.f16.f32 "
        "{%0,%1,%2,%3}, {%4,%5,%6,%7}, {%8,%9}, {%0,%1,%2,%3};\n"
        : "+f"(d[0]), "+f"(d[1]), "+f"(d[2]), "+f"(d[3])
        : "r"(a[0]), "r"(a[1]), "r"(a[2]), "r"(a[3]),
          "r"(b[0]), "r"(b[1]));
}

__device__ __forceinline__ unsigned smem_u32(const void* p) {
    return (unsigned)__cvta_generic_to_shared(p);
}

__device__ __forceinline__ void ldsm4(float* r, unsigned addr) {
    unsigned* u = (unsigned*)r;
    asm volatile("ldmatrix.sync.aligned.m8n8.x4.shared.b16 {%0,%1,%2,%3}, [%4];"
                 : "=r"(u[0]), "=r"(u[1]), "=r"(u[2]), "=r"(u[3]) : "r"(addr));
}
__device__ __forceinline__ void ldsm4u(unsigned* u, unsigned addr) {
    asm volatile("ldmatrix.sync.aligned.m8n8.x4.shared.b16 {%0,%1,%2,%3}, [%4];"
                 : "=r"(u[0]), "=r"(u[1]), "=r"(u[2]), "=r"(u[3]) : "r"(addr));
}

#define CP16(dst, src) \
    asm volatile("cp.async.cg.shared.global [%0], [%1], 16;" :: "r"(dst), "l"(src))
#define CPCOMMIT() asm volatile("cp.async.commit_group;")
#define CPWAIT1()  asm volatile("cp.async.wait_group 1;" ::: "memory")
#define CPWAIT0()  asm volatile("cp.async.wait_group 0;" ::: "memory")

// ---------------------------------------------------------------------------
// float -> half conversion (x, w; once)
// ---------------------------------------------------------------------------
__global__ void to_half_kernel(const float4* __restrict__ src,
                               __half2* __restrict__ dst, int n4)
{
    for (int i = blockIdx.x * blockDim.x + threadIdx.x; i < n4;
         i += gridDim.x * blockDim.x) {
        float4 v = src[i];
        dst[2 * i]     = __floats2half2_rn(v.x, v.y);
        dst[2 * i + 1] = __floats2half2_rn(v.z, v.w);
    }
}

// ---------------------------------------------------------------------------
// fp16 GEMM (TN): C[m][n] = sum_k A[m*K+k] * B[n*K+k], fp32 accumulate.
// 128x128 tile, BK=64 (rows of 128B), 8 warps (2x4), warp tile 64x32.
// 3-stage cp.async ring, one barrier/iter, m16n8k16 mma, paired-B ldmatrix.x4.
// Pitch 72 halves (144B): ldmatrix rows at 4-bank offsets — conflict-free.
// Byte-level layout identical to the validated tf32 kernel.
// fuse==1: fused RMSNorm+RoPE / v-blend epilogue -> tf32 floats (g_qkv).
// ---------------------------------------------------------------------------
#define HSPAD   72                  // halves per row (144 B)
#define HSTG    (128 * HSPAD)       // halves per operand per stage
#define GSTAGES 3
#define GEMM_SMEM (GSTAGES * 2 * HSTG * 2)   // 110,592 B

__global__ __launch_bounds__(256, 2)
void gemm_f16_kernel(const __half* __restrict__ A,
                     const __half* __restrict__ B,
                     float* __restrict__ C,
                     int M, int N, int K, int fuse,
                     const float* __restrict__ ve,
                     const float* __restrict__ lam)
{
    extern __shared__ float smg[];
    __half* As = (__half*)smg;                 // [3][128][72]
    __half* Bs = As + GSTAGES * HSTG;

    const int tid  = threadIdx.x;
    const int lane = tid & 31;
    const int wid  = tid >> 5;
    const int g    = lane >> 2;
    const int tig  = lane & 3;
    const int wm   = (wid & 1) * 64;
    const int wn   = (wid >> 1) * 32;

    const int rowBase = blockIdx.y * 128;
    const int colBase = blockIdx.x * 128;
    const __half* Ag = A + (size_t)rowBase * K;
    const __half* Bg = B + (size_t)colBase * K;

    // ldmatrix lane addressing (bytes identical to validated tf32 scheme)
    const int arow = (lane & 7) + ((lane >> 3) & 1) * 8;
    const int acol = (lane >> 4) * 8;              // halves (=16B)
    const int tl   = lane >> 3;
    const int brow = (lane & 7) + (tl >> 1) * 8;
    const int bcol = (tl & 1) * 8;                 // halves (=16B)

    unsigned aAddr[4], bAddr[2];
#pragma unroll
    for (int mi = 0; mi < 4; mi++)
        aAddr[mi] = smem_u32(&As[(wm + mi * 16 + arow) * HSPAD + acol]);
#pragma unroll
    for (int p = 0; p < 2; p++)
        bAddr[p] = smem_u32(&Bs[(wn + p * 16 + brow) * HSPAD + bcol]);

    const unsigned asA = smem_u32(As);
    const unsigned asB = smem_u32(Bs);
    const unsigned STGB = HSTG * 2;                // bytes per stage (18,432)

    float acc[4][4][4];
#pragma unroll
    for (int mi = 0; mi < 4; mi++)
#pragma unroll
        for (int ni = 0; ni < 4; ni++)
#pragma unroll
            for (int c = 0; c < 4; c++) acc[mi][ni][c] = 0.0f;

    const int nk = K >> 6;   // BK=64 halves (=128B rows)

    // per-stage load: 128 rows x 128B = 1024 CP16 per operand (4/thread)
#define H_LOAD(chunk, stage)                                                   \
    do {                                                                       \
        const unsigned so = (unsigned)(stage) * STGB;                          \
        const size_t kh = (size_t)(chunk) * 64;                                \
        _Pragma("unroll")                                                      \
        for (int j = 0; j < 4; j++) {                                          \
            int f = tid + 256 * j;                                             \
            int row = f >> 3;                                                  \
            int seg = (f & 7) << 4;                                            \
            CP16(asA + so + (unsigned)(row * 144 + seg),                       \
                 (const char*)(Ag + (size_t)row * K + kh) + seg);              \
            CP16(asB + so + (unsigned)(row * 144 + seg),                       \
                 (const char*)(Bg + (size_t)row * K + kh) + seg);              \
        }                                                                      \
        CPCOMMIT();                                                            \
    } while (0)

    H_LOAD(0, 0);
    H_LOAD(1, 1);

    int slot = 0;
    for (int kt = 0; kt < nk; kt++) {
        CPWAIT1();
        __syncthreads();

        if (kt + GSTAGES - 1 < nk) {
            H_LOAD(kt + GSTAGES - 1, (kt + GSTAGES - 1) % GSTAGES);
        } else {
            CPCOMMIT();   // keep group count exact
        }

        const unsigned cOff = (unsigned)slot * STGB;
#pragma unroll
        for (int ks = 0; ks < 4; ks++) {          // 4 k16-steps per BK=64
            const unsigned kOff = cOff + ks * 32; // 16 halves = 32 B
            unsigned a[4][4], bq[2][4];
#pragma unroll
            for (int mi = 0; mi < 4; mi++) ldsm4u(a[mi], aAddr[mi] + kOff);
#pragma unroll
            for (int p = 0; p < 2; p++) ldsm4u(bq[p], bAddr[p] + kOff);
#pragma unroll
            for (int mi = 0; mi < 4; mi++)
#pragma unroll
                for (int p = 0; p < 2; p++) {
                    mma_f16(acc[mi][2 * p],     a[mi], &bq[p][0]);
                    mma_f16(acc[mi][2 * p + 1], a[mi], &bq[p][2]);
                }
        }
        slot = (slot + 1 == GSTAGES) ? 0 : slot + 1;
    }
#undef H_LOAD

    if (!fuse) {
        float* Cp = C + (size_t)rowBase * N + colBase;
#pragma unroll
        for (int mi = 0; mi < 4; mi++) {
            int m = wm + mi * 16 + g;
#pragma unroll
            for (int ni = 0; ni < 4; ni++) {
                int n = wn + ni * 8 + tig * 2;
                *(float2*)&Cp[(size_t)m * N + n] =
                    make_float2(acc[mi][ni][0], acc[mi][ni][1]);
                *(float2*)&Cp[(size_t)(m + 8) * N + n] =
                    make_float2(acc[mi][ni][2], acc[mi][ni][3]);
            }
        }
        return;
    }

    // fused epilogue: RMSNorm + RoPE / v-blend (proven); writes tf32 floats
    __syncthreads();
    float* Cs = smg;                 // [128][132] = 67,584 B
#pragma unroll
    for (int mi = 0; mi < 4; mi++) {
        int m = wm + mi * 16 + g;
#pragma unroll
        for (int ni = 0; ni < 4; ni++) {
            int n = wn + ni * 8 + tig * 2;
            *(float2*)&Cs[m * 132 + n] =
                make_float2(acc[mi][ni][0], acc[mi][ni][1]);
            *(float2*)&Cs[(m + 8) * 132 + n] =
                make_float2(acc[mi][ni][2], acc[mi][ni][3]);
        }
    }
    __syncthreads();

    const int e = colBase >> 11;               // 0=q 1=k 2=v
    const float lam0 = (e == 2) ? lam[0] : 0.0f;
    const float lam1 = (e == 2) ? lam[1] : 0.0f;

    for (int rr = 0; rr < 16; rr++) {
        const int r = wid * 16 + rr;
        const int t = rowBase + r;
        float4 v = *(const float4*)&Cs[r * 132 + lane * 4];
        float ss = v.x * v.x + v.y * v.y + v.z * v.z + v.w * v.w;
#pragma unroll
        for (int o = 16; o > 0; o >>= 1)
            ss += __shfl_xor_sync(0xffffffffu, ss, o);
        const float rinv = rsqrtf(ss * (1.0f / 128.0f) + 1e-6f);

        float o4[4];
        const float* vp = (const float*)&v;
        if (e < 2) {
#pragma unroll
            for (int q = 0; q < 4; q++) {
                int c = lane * 4 + q;
                int j = c & 63;
                float cur = vp[q] * rinv;
                float par = Cs[r * 132 + (c ^ 64)] * rinv;
                float cs, sn;
                if (j < 32) {
                    float fr = exp2f((-10.0f / 31.0f) * (float)j);
                    float th = (float)t * fr;
                    cs = cosf(th); sn = sinf(th);
                } else { cs = 1.0f; sn = 0.0f; }
                o4[q] = (c < 64) ? (cur * cs + par * sn) : (cur * cs - par * sn);
            }
        } else {
            float4 vv = *(const float4*)(ve + (size_t)t * DIM_C +
                                         (colBase & 2047) + lane * 4);
            const float* vvp = (const float*)&vv;
#pragma unroll
            for (int q = 0; q < 4; q++)
                o4[q] = lam0 * (vp[q] * rinv) + lam1 * vvp[q];
        }
        *(float4*)&C[(size_t)t * N + colBase + lane * 4] =
            make_float4(tf32r(o4[0]), tf32r(o4[1]), tf32r(o4[2]), tf32r(o4[3]));
    }
}

// ---------------------------------------------------------------------------
// Causal flash attention v3 (proven in R15). Only change: epilogue emits fp16
// y into g_yh for the fp16 output GEMM.
// ---------------------------------------------------------------------------
#define KSTR  (64 * 132)
#define VSTR  (128 * 68)
#define AQ3_OFF 0
#define AK3_OFF (128 * 132)
#define AV3_OFF (AK3_OFF + 2 * KSTR)
#define ATTN_SMEM3 ((AV3_OFF + 2 * VSTR) * 4)   // 204,800 B

__global__ __launch_bounds__(256, 1)
void attn_kernel()
{
    extern __shared__ float sm[];
    float* Qs  = sm + AQ3_OFF;
    float* Ks  = sm + AK3_OFF;    // [2][64][132]
    float* Vst = sm + AV3_OFF;    // [2][128][68]

    const int h     = blockIdx.y;
    const int qt    = 15 - (int)blockIdx.x;
    const int qbase = qt * 128;
    const int tid   = threadIdx.x;
    const int lane  = tid & 31;
    const int wid   = tid >> 5;
    const int g     = lane >> 2;
    const int tig   = lane & 3;
    const int rw    = wid * 16;

    const int arow = (lane & 7) + ((lane >> 3) & 1) * 8;
    const int acol = (lane >> 4) * 4;
    const int tl   = lane >> 3;
    const int brow = (lane & 7) + (tl >> 1) * 8;
    const int bcol = (tl & 1) * 4;

    const unsigned qAddr = smem_u32(&Qs[(rw + arow) * 132 + acol]);
    unsigned kA[2][4], vA[2][8];
#pragma unroll
    for (int b = 0; b < 2; b++) {
#pragma unroll
        for (int p = 0; p < 4; p++)
            kA[b][p] = smem_u32(&Ks[b * KSTR + (p * 16 + brow) * 132 + bcol]);
#pragma unroll
        for (int p = 0; p < 8; p++)
            vA[b][p] = smem_u32(&Vst[b * VSTR + (p * 16 + brow) * 68 + bcol]);
    }
    const unsigned ksB0 = smem_u32(Ks);
    const unsigned ksB1 = smem_u32(Ks + KSTR);

    const float* qg = g_qkv + (size_t)qbase * QKV_N + h * HD;
#pragma unroll
    for (int f = tid; f < 128 * 32; f += 256) {
        int r = f >> 5, d4 = (f & 31) << 2;
        *(float4*)&Qs[r * 132 + d4] = *(const float4*)(qg + (size_t)r * QKV_N + d4);
    }

    // initial K0 (full 32KB: 8 CP16/thread) + V0 transpose
    {
        const float* kg = g_qkv + 2048 + h * HD;
#pragma unroll
        for (int f = tid; f < 64 * 32; f += 256) {
            int c = f >> 5, seg = (f & 31) << 4;
            CP16(ksB0 + (unsigned)(c * 132 * 4 + seg),
                 (const char*)(kg + (size_t)c * QKV_N) + seg);
        }
        CPCOMMIT();
        const float* vg = g_qkv + 4096 + h * HD;
#pragma unroll
        for (int f = tid; f < 64 * 32; f += 256) {
            int d4 = (f >> 6) << 2, c = f & 63;
            float4 v = *(const float4*)(vg + (size_t)c * QKV_N + d4);
            Vst[(d4 + 0) * 68 + c] = v.x;
            Vst[(d4 + 1) * 68 + c] = v.y;
            Vst[(d4 + 2) * 68 + c] = v.z;
            Vst[(d4 + 3) * 68 + c] = v.w;
        }
    }

    float oacc[16][4];
#pragma unroll
    for (int nd = 0; nd < 16; nd++)
#pragma unroll
        for (int c = 0; c < 4; c++) oacc[nd][c] = 0.0f;

    float m0 = -INFINITY, m1 = -INFINITY, l0 = 0.0f, l1 = 0.0f;
    const int row0 = qbase + rw + g;
    const int row1 = row0 + 8;

    CPWAIT0();
    __syncthreads();

    const int nkv = 2 * qt + 2;
    for (int kb = 0; kb < nkv; kb++) {
        const int buf = kb & 1;
        const bool pre = (kb + 1 < nkv);

        if (pre) {
            const float* kg = g_qkv + (size_t)((kb + 1) * 64) * QKV_N + 2048 + h * HD;
            const unsigned kd = buf ? ksB0 : ksB1;
#pragma unroll
            for (int f = tid; f < 64 * 32; f += 256) {
                int c = f >> 5, seg = (f & 31) << 4;
                CP16(kd + (unsigned)(c * 132 * 4 + seg),
                     (const char*)(kg + (size_t)c * QKV_N) + seg);
            }
        }
        CPCOMMIT();

        float sacc[8][4];
#pragma unroll
        for (int ni = 0; ni < 8; ni++)
#pragma unroll
            for (int c = 0; c < 4; c++) sacc[ni][c] = 0.0f;

#pragma unroll
        for (int kk = 0; kk < 16; kk++) {
            float a[4], bq[4];
            ldsm4(a, qAddr + kk * 32);
#pragma unroll
            for (int p = 0; p < 4; p++) {
                ldsm4(bq, kA[buf][p] + kk * 32);
                mma_tf32(sacc[2 * p],     a, &bq[0]);
                mma_tf32(sacc[2 * p + 1], a, &bq[2]);
            }
        }

        float4 vreg[8];
        if (pre) {
            const float* vg = g_qkv + (size_t)((kb + 1) * 64) * QKV_N + 4096 + h * HD;
#pragma unroll
            for (int j = 0; j < 8; j++) {
                int f = tid + 256 * j;
                int d4 = (f >> 6) << 2, c = f & 63;
                vreg[j] = *(const float4*)(vg + (size_t)c * QKV_N + d4);
            }
        }

        const bool needmask = (kb >= 2 * qt);
        float rmax0 = -INFINITY, rmax1 = -INFINITY;
#pragma unroll
        for (int ni = 0; ni < 8; ni++) {
            int c0 = kb * 64 + ni * 8 + 2 * tig;
            float v0 = sacc[ni][0] * ATTN_SCALE;
            float v1 = sacc[ni][1] * ATTN_SCALE;
            float v2 = sacc[ni][2] * ATTN_SCALE;
            float v3 = sacc[ni][3] * ATTN_SCALE;
            if (needmask) {
                if (c0     > row0) v0 = -INFINITY;
                if (c0 + 1 > row0) v1 = -INFINITY;
                if (c0     > row1) v2 = -INFINITY;
                if (c0 + 1 > row1) v3 = -INFINITY;
            }
            sacc[ni][0] = v0; sacc[ni][1] = v1;
            sacc[ni][2] = v2; sacc[ni][3] = v3;
            rmax0 = fmaxf(rmax0, fmaxf(v0, v1));
            rmax1 = fmaxf(rmax1, fmaxf(v2, v3));
        }
        rmax0 = fmaxf(rmax0, __shfl_xor_sync(0xffffffffu, rmax0, 1));
        rmax0 = fmaxf(rmax0, __shfl_xor_sync(0xffffffffu, rmax0, 2));
        rmax1 = fmaxf(rmax1, __shfl_xor_sync(0xffffffffu, rmax1, 1));
        rmax1 = fmaxf(rmax1, __shfl_xor_sync(0xffffffffu, rmax1, 2));

        float mn0 = fmaxf(m0, rmax0);
        float mn1 = fmaxf(m1, rmax1);
        float fr0 = __expf(m0 - mn0);
        float fr1 = __expf(m1 - mn1);
        m0 = mn0; m1 = mn1;

        float sum0 = 0.0f, sum1 = 0.0f;
#pragma unroll
        for (int ni = 0; ni < 8; ni++) {
            float p0 = __expf(sacc[ni][0] - mn0);
            float p1 = __expf(sacc[ni][1] - mn0);
            float p2 = __expf(sacc[ni][2] - mn1);
            float p3 = __expf(sacc[ni][3] - mn1);
            sum0 += p0 + p1;
            sum1 += p2 + p3;
            sacc[ni][0] = tf32r(p0); sacc[ni][1] = tf32r(p1);
            sacc[ni][2] = tf32r(p2); sacc[ni][3] = tf32r(p3);
        }
        sum0 += __shfl_xor_sync(0xffffffffu, sum0, 1);
        sum0 += __shfl_xor_sync(0xffffffffu, sum0, 2);
        sum1 += __shfl_xor_sync(0xffffffffu, sum1, 1);
        sum1 += __shfl_xor_sync(0xffffffffu, sum1, 2);
        l0 = l0 * fr0 + sum0;
        l1 = l1 * fr1 + sum1;

#pragma unroll
        for (int nd = 0; nd < 16; nd++) {
            oacc[nd][0] *= fr0; oacc[nd][1] *= fr0;
            oacc[nd][2] *= fr1; oacc[nd][3] *= fr1;
        }

        const int src0 = (lane & ~3) | (tig >> 1);
        const int src2 = src0 + 2;
        const bool odd = tig & 1;
#pragma unroll
        for (int sg = 0; sg < 8; sg++) {
            float e0 = __shfl_sync(0xffffffffu, sacc[sg][0], src0);
            float e1 = __shfl_sync(0xffffffffu, sacc[sg][1], src0);
            float e2 = __shfl_sync(0xffffffffu, sacc[sg][2], src0);
            float e3 = __shfl_sync(0xffffffffu, sacc[sg][3], src0);
            float f0 = __shfl_sync(0xffffffffu, sacc[sg][0], src2);
            float f1 = __shfl_sync(0xffffffffu, sacc[sg][1], src2);
            float f2 = __shfl_sync(0xffffffffu, sacc[sg][2], src2);
            float f3 = __shfl_sync(0xffffffffu, sacc[sg][3], src2);
            float a[4];
            a[0] = odd ? e1 : e0;
            a[1] = odd ? e3 : e2;
            a[2] = odd ? f1 : f0;
            a[3] = odd ? f3 : f2;
#pragma unroll
            for (int p = 0; p < 8; p++) {
                float bq[4];
                ldsm4(bq, vA[buf][p] + sg * 32);
                mma_tf32(oacc[2 * p],     a, &bq[0]);
                mma_tf32(oacc[2 * p + 1], a, &bq[2]);
            }
        }

        if (pre) {
            float* vd = Vst + (buf ? 0 : VSTR);
#pragma unroll
            for (int j = 0; j < 8; j++) {
                int f = tid + 256 * j;
                int d4 = (f >> 6) << 2, c = f & 63;
                vd[(d4 + 0) * 68 + c] = vreg[j].x;
                vd[(d4 + 1) * 68 + c] = vreg[j].y;
                vd[(d4 + 2) * 68 + c] = vreg[j].z;
                vd[(d4 + 3) * 68 + c] = vreg[j].w;
            }
        }
        CPWAIT0();
        __syncthreads();
    }

    // epilogue: normalize, emit fp16 y
    const float inv0 = 1.0f / l0;
    const float inv1 = 1.0f / l1;
    __half* dst0 = g_yh + (size_t)row0 * DIM_C + h * HD;
    __half* dst1 = g_yh + (size_t)row1 * DIM_C + h * HD;
#pragma unroll
    for (int nd = 0; nd < 16; nd++) {
        int col = nd * 8 + 2 * tig;
        *(__half2*)&dst0[col] =
            __floats2half2_rn(oacc[nd][0] * inv0, oacc[nd][1] * inv0);
        *(__half2*)&dst1[col] =
            __floats2half2_rn(oacc[nd][2] * inv1, oacc[nd][3] * inv1);
    }
}

// ---------------------------------------------------------------------------
extern "C" void kernel_launch(void* const* d_in, const int* in_sizes, int n_in,
                              void* d_out, int out_size)
{
    const float* x   = (const float*)d_in[0];   // [1,2048,2048]
    const float* w   = (const float*)d_in[1];   // [4,2048,2048]
    const float* ve  = (const float*)d_in[2];   // [1,2048,2048]
    const float* lam = (const float*)d_in[3];   // [2]
    float* out = (float*)d_out;                 // [1,2048,2048] f32

    float  *qkv_ptr = nullptr;
    __half *xh_ptr = nullptr, *wh_ptr = nullptr, *yh_ptr = nullptr;
    cudaGetSymbolAddress((void**)&qkv_ptr, g_qkv);
    cudaGetSymbolAddress((void**)&xh_ptr,  g_xh);
    cudaGetSymbolAddress((void**)&wh_ptr,  g_wh);
    cudaGetSymbolAddress((void**)&yh_ptr,  g_yh);

    // 0) convert x, w to fp16
    to_half_kernel<<<2048, 256>>>((const float4*)x, (__half2*)xh_ptr,
                                  T_SEQ * DIM_C / 4);
    to_half_kernel<<<4096, 256>>>((const float4*)w, (__half2*)wh_ptr,
                                  4 * DIM_C * DIM_C / 4);

    cudaFuncSetAttribute(gemm_f16_kernel,
                         cudaFuncAttributeMaxDynamicSharedMemorySize, GEMM_SMEM);

    // 1) QKV projection (fp16 mma) + fused RMSNorm/RoPE/v-blend -> g_qkv
    gemm_f16_kernel<<<dim3(48, 16), 256, GEMM_SMEM>>>(
        xh_ptr, wh_ptr, qkv_ptr, 2048, 6144, 2048, 1, ve, lam);

    // 2) causal attention (tf32; writes fp16 y)
    cudaFuncSetAttribute(attn_kernel,
                         cudaFuncAttributeMaxDynamicSharedMemorySize, ATTN_SMEM3);
    attn_kernel<<<dim3(16, 16), 256, ATTN_SMEM3>>>();

    // 3) output projection (fp16 mma)
    gemm_f16_kernel<<<dim3(16, 16), 256, GEMM_SMEM>>>(
        yh_ptr, wh_ptr + (size_t)3 * DIM_C * DIM_C, out, 2048, 2048, 2048,
        0, nullptr, nullptr);
}